// round 1
// baseline (speedup 1.0000x reference)
#include <cuda_runtime.h>

// Problem constants
#define L_DIM 131072
#define N_DIM 256
#define H_DIM 256
#define CS    256            // scan chunk size (must be multiple of BM)
#define NC    (L_DIM / CS)   // 512 chunks

// GEMM tiling
#define BM 128
#define BN 64
#define BK 32

// ---------------- scratch (static device allocations; no cudaMalloc) -------
__device__ float g_bu_re[(size_t)L_DIM * N_DIM];   // 134 MB
__device__ float g_bu_im[(size_t)L_DIM * N_DIM];   // 134 MB
__device__ float g_lam_re[N_DIM];
__device__ float g_lam_im[N_DIM];
__device__ float g_gamma[N_DIM];
__device__ float g_pow_re[(CS + 1) * N_DIM];       // Lambda^p, p = 0..CS
__device__ float g_pow_im[(CS + 1) * N_DIM];
__device__ float g_ccar_re[NC * N_DIM];            // local chunk-end states
__device__ float g_ccar_im[NC * N_DIM];
__device__ float g_carry_re[NC * N_DIM];           // exclusive carry-in per chunk
__device__ float g_carry_im[NC * N_DIM];

// ---------------- K0: parameters + Lambda power table ----------------------
__global__ void k_setup(const float* __restrict__ nu_log,
                        const float* __restrict__ theta_log,
                        const float* __restrict__ gamma_log)
{
    int n = threadIdx.x;
    if (n >= N_DIM) return;
    double nu  = exp((double)nu_log[n]);
    double th  = exp((double)theta_log[n]);
    double mag = exp(-nu);
    double lr  = mag * cos(th);
    double li  = mag * sin(th);
    g_lam_re[n] = (float)lr;
    g_lam_im[n] = (float)li;
    g_gamma[n]  = expf(gamma_log[n]);
    double pr = 1.0, pi = 0.0;
    for (int p = 0; p <= CS; p++) {
        g_pow_re[p * N_DIM + n] = (float)pr;
        g_pow_im[p * N_DIM + n] = (float)pi;
        double t = pr * lr - pi * li;
        pi = pr * li + pi * lr;
        pr = t;
    }
}

// ---------------- K1: Bu = x @ (gamma * B)^T  (complex output) -------------
// Bu_re[l][n] = sum_h x[l][h] * B_re[n][h] * gamma[n]   (same for im)
__global__ __launch_bounds__(256) void k_gemm1(const float* __restrict__ x,
                                               const float* __restrict__ Bre,
                                               const float* __restrict__ Bim)
{
    __shared__ float xs[BM * BK];
    __shared__ float bsr[BK * BN];
    __shared__ float bsi[BK * BN];

    int tid = threadIdx.x;
    int bx = blockIdx.x;            // n tile (4)
    int by = blockIdx.y;            // row tile (1024)
    int rowBase = by * BM;
    int colBase = bx * BN;
    int tx = tid & 15;              // 16 -> 4 cols each
    int ty = tid >> 4;              // 16 -> 8 rows each

    float accr[8][4], acci[8][4];
#pragma unroll
    for (int i = 0; i < 8; i++)
#pragma unroll
        for (int j = 0; j < 4; j++) { accr[i][j] = 0.f; acci[i][j] = 0.f; }

    for (int k0 = 0; k0 < H_DIM; k0 += BK) {
        // x tile: 128 rows x 32 k = 1024 float4
#pragma unroll
        for (int i = 0; i < 4; i++) {
            int id = tid + 256 * i;
            int r  = id >> 3;
            int f4 = id & 7;
            float4 v = *(const float4*)(x + (size_t)(rowBase + r) * H_DIM + k0 + f4 * 4);
            *(float4*)(xs + r * BK + f4 * 4) = v;
        }
        // B tiles (re & im): 64 n x 32 k each -> transposed into [k][n]
#pragma unroll
        for (int i = 0; i < 4; i++) {
            int id  = tid + 256 * i;       // 0..1023
            int mat = id >> 9;             // 0: re, 1: im
            int nn  = (id >> 3) & 63;
            int f4  = id & 7;
            const float* src = mat ? Bim : Bre;
            float g = g_gamma[colBase + nn];
            float4 v = *(const float4*)(src + (size_t)(colBase + nn) * H_DIM + k0 + f4 * 4);
            float* dst = mat ? bsi : bsr;
            dst[(f4 * 4 + 0) * BN + nn] = v.x * g;
            dst[(f4 * 4 + 1) * BN + nn] = v.y * g;
            dst[(f4 * 4 + 2) * BN + nn] = v.z * g;
            dst[(f4 * 4 + 3) * BN + nn] = v.w * g;
        }
        __syncthreads();
#pragma unroll
        for (int k = 0; k < BK; k++) {
            float xv[8];
#pragma unroll
            for (int i = 0; i < 8; i++) xv[i] = xs[(ty * 8 + i) * BK + k];
            float4 brv = *(float4*)(bsr + k * BN + tx * 4);
            float4 biv = *(float4*)(bsi + k * BN + tx * 4);
            float br[4] = {brv.x, brv.y, brv.z, brv.w};
            float bi[4] = {biv.x, biv.y, biv.z, biv.w};
#pragma unroll
            for (int i = 0; i < 8; i++)
#pragma unroll
                for (int j = 0; j < 4; j++) {
                    accr[i][j] = fmaf(xv[i], br[j], accr[i][j]);
                    acci[i][j] = fmaf(xv[i], bi[j], acci[i][j]);
                }
        }
        __syncthreads();
    }
#pragma unroll
    for (int i = 0; i < 8; i++) {
        int l = rowBase + ty * 8 + i;
        float4 vr = make_float4(accr[i][0], accr[i][1], accr[i][2], accr[i][3]);
        float4 vi = make_float4(acci[i][0], acci[i][1], acci[i][2], acci[i][3]);
        *(float4*)(g_bu_re + (size_t)l * N_DIM + colBase + tx * 4) = vr;
        *(float4*)(g_bu_im + (size_t)l * N_DIM + colBase + tx * 4) = vi;
    }
}

// ---------------- K2a: per-chunk local scan (in place) ---------------------
__global__ __launch_bounds__(256) void k_scan_local()
{
    int chunk = blockIdx.x;
    int n = threadIdx.x;
    float lr = g_lam_re[n], li = g_lam_im[n];
    size_t base = (size_t)chunk * CS * N_DIM + n;
    float zr = 0.f, zi = 0.f;
#pragma unroll 8
    for (int s = 0; s < CS; s++) {
        float br = g_bu_re[base];
        float bi = g_bu_im[base];
        float nzr = fmaf(lr, zr, fmaf(-li, zi, br));
        float nzi = fmaf(lr, zi, fmaf( li, zr, bi));
        zr = nzr; zi = nzi;
        g_bu_re[base] = zr;
        g_bu_im[base] = zi;
        base += N_DIM;
    }
    g_ccar_re[chunk * N_DIM + n] = zr;
    g_ccar_im[chunk * N_DIM + n] = zi;
}

// ---------------- K2b: carry scan across chunks ----------------------------
__global__ void k_scan_carry()
{
    int n = threadIdx.x;
    float ar = g_pow_re[CS * N_DIM + n];   // Lambda^CS
    float ai = g_pow_im[CS * N_DIM + n];
    float cr = 0.f, ci = 0.f;
#pragma unroll 4
    for (int c = 0; c < NC; c++) {
        g_carry_re[c * N_DIM + n] = cr;    // exclusive prefix = carry-in
        g_carry_im[c * N_DIM + n] = ci;
        float er = g_ccar_re[c * N_DIM + n];
        float ei = g_ccar_im[c * N_DIM + n];
        float tr = fmaf(ar, cr, fmaf(-ai, ci, er));
        ci       = fmaf(ar, ci, fmaf( ai, cr, ei));
        cr = tr;
    }
}

// ---------------- K3: y = Re(C @ z) + D*x  (carry correction fused) --------
// z[l][n] = z_local[l][n] + Lambda^{(l%CS)+1} * carry_in[l/CS][n]
__global__ __launch_bounds__(256) void k_gemm2(const float* __restrict__ x,
                                               const float* __restrict__ Cre,
                                               const float* __restrict__ Cim,
                                               const float* __restrict__ Dv,
                                               float* __restrict__ out)
{
    __shared__ float zsr[BM * BK];
    __shared__ float zsi[BM * BK];
    __shared__ float csr[BK * BN];
    __shared__ float csi[BK * BN];

    int tid = threadIdx.x;
    int bx = blockIdx.x;            // h tile (4)
    int by = blockIdx.y;            // row tile (1024)
    int rowBase = by * BM;
    int colBase = bx * BN;
    int chunk = rowBase / CS;       // whole 128-row tile lies in one chunk
    int tx = tid & 15;
    int ty = tid >> 4;

    float acc[8][4];
#pragma unroll
    for (int i = 0; i < 8; i++)
#pragma unroll
        for (int j = 0; j < 4; j++) acc[i][j] = 0.f;

    for (int k0 = 0; k0 < N_DIM; k0 += BK) {
        // z tile with carry correction: 128 rows x 32 n (re & im)
#pragma unroll
        for (int i = 0; i < 4; i++) {
            int id = tid + 256 * i;
            int r  = id >> 3;
            int f4 = id & 7;
            int l  = rowBase + r;
            int sp = (l & (CS - 1)) + 1;         // local index + 1
            int n0 = k0 + f4 * 4;
            float4 br = *(const float4*)(g_bu_re   + (size_t)l * N_DIM + n0);
            float4 bi = *(const float4*)(g_bu_im   + (size_t)l * N_DIM + n0);
            float4 pr = *(const float4*)(g_pow_re  + sp * N_DIM + n0);
            float4 pi = *(const float4*)(g_pow_im  + sp * N_DIM + n0);
            float4 cr = *(const float4*)(g_carry_re + chunk * N_DIM + n0);
            float4 ci = *(const float4*)(g_carry_im + chunk * N_DIM + n0);
            float4 zr, zi;
            zr.x = br.x + pr.x * cr.x - pi.x * ci.x;  zi.x = bi.x + pr.x * ci.x + pi.x * cr.x;
            zr.y = br.y + pr.y * cr.y - pi.y * ci.y;  zi.y = bi.y + pr.y * ci.y + pi.y * cr.y;
            zr.z = br.z + pr.z * cr.z - pi.z * ci.z;  zi.z = bi.z + pr.z * ci.z + pi.z * cr.z;
            zr.w = br.w + pr.w * cr.w - pi.w * ci.w;  zi.w = bi.w + pr.w * ci.w + pi.w * cr.w;
            *(float4*)(zsr + r * BK + f4 * 4) = zr;
            *(float4*)(zsi + r * BK + f4 * 4) = zi;
        }
        // C tiles: 64 h x 32 n (re & im) -> transposed into [n][h]
#pragma unroll
        for (int i = 0; i < 4; i++) {
            int id  = tid + 256 * i;
            int mat = id >> 9;
            int hh  = (id >> 3) & 63;
            int f4  = id & 7;
            const float* src = mat ? Cim : Cre;
            float4 v = *(const float4*)(src + (size_t)(colBase + hh) * N_DIM + k0 + f4 * 4);
            float* dst = mat ? csi : csr;
            dst[(f4 * 4 + 0) * BN + hh] = v.x;
            dst[(f4 * 4 + 1) * BN + hh] = v.y;
            dst[(f4 * 4 + 2) * BN + hh] = v.z;
            dst[(f4 * 4 + 3) * BN + hh] = v.w;
        }
        __syncthreads();
#pragma unroll
        for (int k = 0; k < BK; k++) {
            float zr[8], zi[8];
#pragma unroll
            for (int i = 0; i < 8; i++) {
                zr[i] = zsr[(ty * 8 + i) * BK + k];
                zi[i] = zsi[(ty * 8 + i) * BK + k];
            }
            float4 crv = *(float4*)(csr + k * BN + tx * 4);
            float4 civ = *(float4*)(csi + k * BN + tx * 4);
            float cr[4] = {crv.x, crv.y, crv.z, crv.w};
            float ci[4] = {civ.x, civ.y, civ.z, civ.w};
#pragma unroll
            for (int i = 0; i < 8; i++)
#pragma unroll
                for (int j = 0; j < 4; j++) {
                    acc[i][j] = fmaf(zr[i], cr[j], acc[i][j]);
                    acc[i][j] = fmaf(-zi[i], ci[j], acc[i][j]);
                }
        }
        __syncthreads();
    }
    // epilogue: + D[h] * x[l][h]
    float4 d4 = *(const float4*)(Dv + colBase + tx * 4);
#pragma unroll
    for (int i = 0; i < 8; i++) {
        int l = rowBase + ty * 8 + i;
        float4 xv = *(const float4*)(x + (size_t)l * H_DIM + colBase + tx * 4);
        float4 o;
        o.x = acc[i][0] + d4.x * xv.x;
        o.y = acc[i][1] + d4.y * xv.y;
        o.z = acc[i][2] + d4.z * xv.z;
        o.w = acc[i][3] + d4.w * xv.w;
        *(float4*)(out + (size_t)l * H_DIM + colBase + tx * 4) = o;
    }
}

// ---------------- launch ---------------------------------------------------
extern "C" void kernel_launch(void* const* d_in, const int* in_sizes, int n_in,
                              void* d_out, int out_size)
{
    const float* x         = (const float*)d_in[0];
    const float* nu_log    = (const float*)d_in[1];
    const float* theta_log = (const float*)d_in[2];
    const float* B_re      = (const float*)d_in[3];
    const float* B_im      = (const float*)d_in[4];
    const float* C_re      = (const float*)d_in[5];
    const float* C_im      = (const float*)d_in[6];
    const float* Dv        = (const float*)d_in[7];
    const float* gamma_log = (const float*)d_in[8];
    float* out = (float*)d_out;

    k_setup<<<1, N_DIM>>>(nu_log, theta_log, gamma_log);
    k_gemm1<<<dim3(N_DIM / BN, L_DIM / BM), 256>>>(x, B_re, B_im);
    k_scan_local<<<NC, N_DIM>>>();
    k_scan_carry<<<1, N_DIM>>>();
    k_gemm2<<<dim3(H_DIM / BN, L_DIM / BM), 256>>>(x, C_re, C_im, Dv, out);
}

// round 2
// speedup vs baseline: 1.6357x; 1.6357x over previous
#include <cuda_runtime.h>
#include <cuda_bf16.h>
#include <cstdint>

// Problem constants
#define L_DIM 131072
#define N_DIM 256
#define H_DIM 256
#define CS    128            // scan chunk size == BM
#define NC    (L_DIM / CS)   // 1024 chunks

// GEMM tiling
#define BM 128
#define BN 64
#define BK 32
#define AST 40               // smem stride (bf16 elems) for A tiles: conflict-free ldmatrix
#define BST 40

// ---------------- static device scratch ------------------------------------
__device__ float g_S[(size_t)L_DIM * 512];            // scanned local states [l][k]: k<256 re, >=256 im (268MB)
__device__ float g_gamma[N_DIM];
__device__ float g_pow_re[(CS + 1) * N_DIM];          // Lambda^p, p=0..128
__device__ float g_pow_im[(CS + 1) * N_DIM];
__device__ float g_cpow_re[10 * N_DIM];               // Lambda^(128*2^d), d=0..9
__device__ float g_cpow_im[10 * N_DIM];
__device__ float2 g_ccar[NC * N_DIM];                 // local chunk-end states
__device__ float2 g_carry[NC * N_DIM];                // exclusive carry per chunk
__device__ __nv_bfloat16 g_B2hi[512 * 256];           // packed gamma*B (rows: 0..255 re, 256..511 im), hi/lo split
__device__ __nv_bfloat16 g_B2lo[512 * 256];
__device__ __nv_bfloat16 g_C2hi[256 * 512];           // packed [Cr | -Ci] per h row, k-contig
__device__ __nv_bfloat16 g_C2lo[256 * 512];

// ---------------- helpers ---------------------------------------------------
__device__ __forceinline__ uint32_t smaddr(const void* p) {
    return (uint32_t)__cvta_generic_to_shared(p);
}
__device__ __forceinline__ void ldsm4(uint32_t& r0, uint32_t& r1, uint32_t& r2, uint32_t& r3, uint32_t a) {
    asm volatile("ldmatrix.sync.aligned.m8n8.x4.shared.b16 {%0,%1,%2,%3}, [%4];"
                 : "=r"(r0), "=r"(r1), "=r"(r2), "=r"(r3) : "r"(a));
}
__device__ __forceinline__ void ldsm2(uint32_t& r0, uint32_t& r1, uint32_t a) {
    asm volatile("ldmatrix.sync.aligned.m8n8.x2.shared.b16 {%0,%1}, [%2];"
                 : "=r"(r0), "=r"(r1) : "r"(a));
}
__device__ __forceinline__ void mma_bf16(float* c, const uint32_t* a, const uint32_t* b) {
    asm volatile("mma.sync.aligned.m16n8k16.row.col.f32.bf16.bf16.f32 "
                 "{%0,%1,%2,%3},{%4,%5,%6,%7},{%8,%9},{%0,%1,%2,%3};"
                 : "+f"(c[0]), "+f"(c[1]), "+f"(c[2]), "+f"(c[3])
                 : "r"(a[0]), "r"(a[1]), "r"(a[2]), "r"(a[3]), "r"(b[0]), "r"(b[1]));
}
__device__ __forceinline__ void split2(float v, __nv_bfloat16& h, __nv_bfloat16& l) {
    h = __float2bfloat16(v);
    l = __float2bfloat16(v - __bfloat162float(h));
}

// ---------------- K0: parameters + power tables -----------------------------
__global__ void k_setup(const float* __restrict__ nu_log,
                        const float* __restrict__ theta_log,
                        const float* __restrict__ gamma_log)
{
    int n = threadIdx.x;
    double nu  = exp((double)nu_log[n]);
    double th  = exp((double)theta_log[n]);
    double mag = exp(-nu);
    double lr  = mag * cos(th);
    double li  = mag * sin(th);
    g_gamma[n] = expf(gamma_log[n]);
    double pr = 1.0, pi = 0.0;
    double cr = 1.0, ci = 0.0;
    for (int p = 0; p <= CS; p++) {
        g_pow_re[p * N_DIM + n] = (float)pr;
        g_pow_im[p * N_DIM + n] = (float)pi;
        if (p == CS) { cr = pr; ci = pi; }
        double t = pr * lr - pi * li;
        pi = pr * li + pi * lr;
        pr = t;
    }
    for (int d = 0; d < 10; d++) {
        g_cpow_re[d * N_DIM + n] = (float)cr;
        g_cpow_im[d * N_DIM + n] = (float)ci;
        double t = cr * cr - ci * ci;
        ci = 2.0 * cr * ci;
        cr = t;
    }
}

// ---------------- K0b: pack B and C into bf16 hi/lo planes -------------------
__global__ void k_pack(const float* __restrict__ Bre, const float* __restrict__ Bim,
                       const float* __restrict__ Cre, const float* __restrict__ Cim)
{
    int b = blockIdx.x;
    int t = threadIdx.x;
    if (b < 512) {
        int n = (b < 256) ? b : b - 256;
        const float* src = (b < 256) ? Bre : Bim;
        float g = g_gamma[n];
        float v = src[n * 256 + t] * g;
        __nv_bfloat16 h, l; split2(v, h, l);
        g_B2hi[b * 256 + t] = h;
        g_B2lo[b * 256 + t] = l;
    } else {
        int h = b - 512;
        for (int k = t; k < 512; k += 256) {
            float v = (k < 256) ? Cre[h * 256 + k] : -Cim[h * 256 + (k - 256)];
            __nv_bfloat16 hh, ll; split2(v, hh, ll);
            g_C2hi[h * 512 + k] = hh;
            g_C2lo[h * 512 + k] = ll;
        }
    }
}

// ---------------- K1: Bu = x @ Bn^T  (mma) + fused local scan ---------------
__global__ __launch_bounds__(256) void k_gemm1(const float* __restrict__ x)
{
    __shared__ union {
        struct {
            __nv_bfloat16 Ah[BM * AST];
            __nv_bfloat16 Al[BM * AST];
            __nv_bfloat16 Bh[BN * BST];
            __nv_bfloat16 Bl[BN * BST];
        } p;
        float zs[BM * 64];
    } sm;

    const int tid  = threadIdx.x;
    const int lane = tid & 31;
    const int warp = tid >> 5;
    const int mw = warp >> 1;           // 0..3
    const int nw = warp & 1;            // 0..1
    const int bx = blockIdx.x;          // 8 channel tiles (32 complex ch each)
    const int by = blockIdx.y;          // 1024 chunks
    const int rowBase = by * BM;

    float acc[2][4][4];
#pragma unroll
    for (int mi = 0; mi < 2; mi++)
#pragma unroll
        for (int ni = 0; ni < 4; ni++)
#pragma unroll
            for (int c = 0; c < 4; c++) acc[mi][ni][c] = 0.f;

    // B global row mapping for this block
    const int browA = tid >> 2;                 // 0..63
    const int bkc   = (tid & 3) * 8;
    const int grow  = (browA < 32) ? (32 * bx + browA) : (224 + 32 * bx + browA);

    for (int k0 = 0; k0 < 256; k0 += BK) {
        // A tile (x) -> split bf16
#pragma unroll
        for (int i = 0; i < 4; i++) {
            int id = tid + 256 * i;
            int r  = id >> 3;
            int f4 = id & 7;
            float4 v = *(const float4*)(x + (size_t)(rowBase + r) * 256 + k0 + f4 * 4);
            __nv_bfloat16 h0, l0, h1, l1, h2, l2, h3, l3;
            split2(v.x, h0, l0); split2(v.y, h1, l1); split2(v.z, h2, l2); split2(v.w, h3, l3);
            __nv_bfloat162* ph = (__nv_bfloat162*)&sm.p.Ah[r * AST + f4 * 4];
            __nv_bfloat162* pl = (__nv_bfloat162*)&sm.p.Al[r * AST + f4 * 4];
            ph[0] = __nv_bfloat162(h0, h1); ph[1] = __nv_bfloat162(h2, h3);
            pl[0] = __nv_bfloat162(l0, l1); pl[1] = __nv_bfloat162(l2, l3);
        }
        // B tiles (pre-split planes)
        {
            uint4 vh = *(const uint4*)(g_B2hi + (size_t)grow * 256 + k0 + bkc);
            uint4 vl = *(const uint4*)(g_B2lo + (size_t)grow * 256 + k0 + bkc);
            *(uint4*)&sm.p.Bh[browA * BST + bkc] = vh;
            *(uint4*)&sm.p.Bl[browA * BST + bkc] = vl;
        }
        __syncthreads();

#pragma unroll
        for (int kk = 0; kk < BK; kk += 16) {
            uint32_t ah[2][4], al[2][4], bh[4][2], bl[4][2];
            const int alr = lane & 15, alc = (lane >> 4) * 8;
            const int bl8 = lane & 7, bc8 = ((lane >> 3) & 1) * 8;
#pragma unroll
            for (int mi = 0; mi < 2; mi++) {
                uint32_t a0 = smaddr(&sm.p.Ah[(mw * 32 + mi * 16 + alr) * AST + kk + alc]);
                ldsm4(ah[mi][0], ah[mi][1], ah[mi][2], ah[mi][3], a0);
                uint32_t a1 = smaddr(&sm.p.Al[(mw * 32 + mi * 16 + alr) * AST + kk + alc]);
                ldsm4(al[mi][0], al[mi][1], al[mi][2], al[mi][3], a1);
            }
#pragma unroll
            for (int ni = 0; ni < 4; ni++) {
                uint32_t b0 = smaddr(&sm.p.Bh[(nw * 32 + ni * 8 + bl8) * BST + kk + bc8]);
                ldsm2(bh[ni][0], bh[ni][1], b0);
                uint32_t b1 = smaddr(&sm.p.Bl[(nw * 32 + ni * 8 + bl8) * BST + kk + bc8]);
                ldsm2(bl[ni][0], bl[ni][1], b1);
            }
#pragma unroll
            for (int mi = 0; mi < 2; mi++)
#pragma unroll
                for (int ni = 0; ni < 4; ni++) {
                    mma_bf16(acc[mi][ni], ah[mi], bh[ni]);
                    mma_bf16(acc[mi][ni], ah[mi], bl[ni]);
                    mma_bf16(acc[mi][ni], al[mi], bh[ni]);
                }
        }
        __syncthreads();
    }

    // ---- write accumulators into zs (overwrites A/B smem) ----
#pragma unroll
    for (int mi = 0; mi < 2; mi++)
#pragma unroll
        for (int ni = 0; ni < 4; ni++)
#pragma unroll
            for (int c = 0; c < 4; c++) {
                int r = mw * 32 + mi * 16 + (lane >> 2) + 8 * (c >> 1);
                int cc = nw * 32 + ni * 8 + 2 * (lane & 3) + (c & 1);
                sm.zs[r * 64 + cc] = acc[mi][ni][c];
            }
    __syncthreads();

    // ---- Kogge-Stone scan over 128 rows (cols: ch re at c, im at c+32) ----
    const int chl   = tid & 31;
    const int chg   = 32 * bx + chl;
    const int rbase = (tid >> 5) * 16;
    float nr[16], nii[16];
#pragma unroll
    for (int d = 0; d < 7; d++) {
        int s = 1 << d;
        float pr = g_pow_re[s * N_DIM + chg];
        float pi = g_pow_im[s * N_DIM + chg];
#pragma unroll
        for (int i = 0; i < 16; i++) {
            int r = rbase + i;
            float zr = sm.zs[r * 64 + chl];
            float zi = sm.zs[r * 64 + 32 + chl];
            if (r >= s) {
                float wr = sm.zs[(r - s) * 64 + chl];
                float wi = sm.zs[(r - s) * 64 + 32 + chl];
                zr = fmaf(pr, wr, fmaf(-pi, wi, zr));
                zi = fmaf(pr, wi, fmaf( pi, wr, zi));
            }
            nr[i] = zr; nii[i] = zi;
        }
        __syncthreads();
#pragma unroll
        for (int i = 0; i < 16; i++) {
            int r = rbase + i;
            sm.zs[r * 64 + chl] = nr[i];
            sm.zs[r * 64 + 32 + chl] = nii[i];
        }
        __syncthreads();
    }

    // ---- store local states + chunk-end carries ----
#pragma unroll
    for (int i = 0; i < 16; i++) {
        int l = rowBase + rbase + i;
        g_S[(size_t)l * 512 + 32 * bx + chl]       = nr[i];
        g_S[(size_t)l * 512 + 256 + 32 * bx + chl] = nii[i];
    }
    if (rbase == 112) {
        g_ccar[by * N_DIM + chg] = make_float2(nr[15], nii[15]);
    }
}

// ---------------- K2: parallel carry scan (per channel) ---------------------
__global__ __launch_bounds__(512) void k_carry()
{
    __shared__ float2 s[NC];
    const int ch = blockIdx.x;
    const int t = threadIdx.x;
    s[t]       = g_ccar[t * N_DIM + ch];
    s[t + 512] = g_ccar[(t + 512) * N_DIM + ch];
    __syncthreads();
#pragma unroll
    for (int d = 0; d < 10; d++) {
        int st = 1 << d;
        float pr = g_cpow_re[d * N_DIM + ch];
        float pi = g_cpow_im[d * N_DIM + ch];
        int c0 = t, c1 = t + 512;
        float2 v0 = s[c0], v1 = s[c1];
        if (c0 >= st) {
            float2 w = s[c0 - st];
            v0.x = fmaf(pr, w.x, fmaf(-pi, w.y, v0.x));
            v0.y = fmaf(pr, w.y, fmaf( pi, w.x, v0.y));
        }
        {
            float2 w = s[c1 - st];
            v1.x = fmaf(pr, w.x, fmaf(-pi, w.y, v1.x));
            v1.y = fmaf(pr, w.y, fmaf( pi, w.x, v1.y));
        }
        __syncthreads();
        s[c0] = v0; s[c1] = v1;
        __syncthreads();
    }
    g_carry[t * N_DIM + ch]         = (t == 0) ? make_float2(0.f, 0.f) : s[t - 1];
    g_carry[(t + 512) * N_DIM + ch] = s[t + 511];
}

// ---------------- K3: y = Re(C z) + D*x  (carry correction fused, mma) ------
__global__ __launch_bounds__(256) void k_gemm2(const float* __restrict__ x,
                                               const float* __restrict__ Dv,
                                               float* __restrict__ out)
{
    __shared__ struct {
        __nv_bfloat16 Ah[BM * AST];
        __nv_bfloat16 Al[BM * AST];
        __nv_bfloat16 Bh[BN * BST];
        __nv_bfloat16 Bl[BN * BST];
    } sm;

    const int tid  = threadIdx.x;
    const int lane = tid & 31;
    const int warp = tid >> 5;
    const int mw = warp >> 1;
    const int nw = warp & 1;
    const int bx = blockIdx.x;          // 4 h tiles of 64
    const int by = blockIdx.y;          // 1024 row tiles (== chunks)
    const int rowBase = by * BM;
    const int colBase = bx * BN;

    float acc[2][4][4];
#pragma unroll
    for (int mi = 0; mi < 2; mi++)
#pragma unroll
        for (int ni = 0; ni < 4; ni++)
#pragma unroll
            for (int c = 0; c < 4; c++) acc[mi][ni][c] = 0.f;

    const int browA = tid >> 2;
    const int bkc   = (tid & 3) * 8;
    const int growC = colBase + browA;

    for (int k0 = 0; k0 < 512; k0 += BK) {
        // A tile: corrected states -> split bf16
#pragma unroll
        for (int i = 0; i < 4; i++) {
            int id = tid + 256 * i;
            int r  = id >> 3;
            int f4 = id & 7;
            int kk = k0 + f4 * 4;
            int half = kk >> 8;
            int n0 = kk & 255;
            float4 sv = *(const float4*)&g_S[(size_t)(rowBase + r) * 512 + kk];
            float4 pwr = *(const float4*)&g_pow_re[(r + 1) * N_DIM + n0];
            float4 pwi = *(const float4*)&g_pow_im[(r + 1) * N_DIM + n0];
            const float2* cp = &g_carry[by * N_DIM + n0];
            float2 c0 = cp[0], c1 = cp[1], c2 = cp[2], c3 = cp[3];
            float v[4];
            if (half == 0) {
                v[0] = sv.x + pwr.x * c0.x - pwi.x * c0.y;
                v[1] = sv.y + pwr.y * c1.x - pwi.y * c1.y;
                v[2] = sv.z + pwr.z * c2.x - pwi.z * c2.y;
                v[3] = sv.w + pwr.w * c3.x - pwi.w * c3.y;
            } else {
                v[0] = sv.x + pwr.x * c0.y + pwi.x * c0.x;
                v[1] = sv.y + pwr.y * c1.y + pwi.y * c1.x;
                v[2] = sv.z + pwr.z * c2.y + pwi.z * c2.x;
                v[3] = sv.w + pwr.w * c3.y + pwi.w * c3.x;
            }
            __nv_bfloat16 h0, l0, h1, l1, h2, l2, h3, l3;
            split2(v[0], h0, l0); split2(v[1], h1, l1); split2(v[2], h2, l2); split2(v[3], h3, l3);
            __nv_bfloat162* ph = (__nv_bfloat162*)&sm.Ah[r * AST + f4 * 4];
            __nv_bfloat162* pl = (__nv_bfloat162*)&sm.Al[r * AST + f4 * 4];
            ph[0] = __nv_bfloat162(h0, h1); ph[1] = __nv_bfloat162(h2, h3);
            pl[0] = __nv_bfloat162(l0, l1); pl[1] = __nv_bfloat162(l2, l3);
        }
        // B tiles (C packed planes)
        {
            uint4 vh = *(const uint4*)(g_C2hi + (size_t)growC * 512 + k0 + bkc);
            uint4 vl = *(const uint4*)(g_C2lo + (size_t)growC * 512 + k0 + bkc);
            *(uint4*)&sm.Bh[browA * BST + bkc] = vh;
            *(uint4*)&sm.Bl[browA * BST + bkc] = vl;
        }
        __syncthreads();

#pragma unroll
        for (int kk = 0; kk < BK; kk += 16) {
            uint32_t ah[2][4], al[2][4], bh[4][2], bl[4][2];
            const int alr = lane & 15, alc = (lane >> 4) * 8;
            const int bl8 = lane & 7, bc8 = ((lane >> 3) & 1) * 8;
#pragma unroll
            for (int mi = 0; mi < 2; mi++) {
                uint32_t a0 = smaddr(&sm.Ah[(mw * 32 + mi * 16 + alr) * AST + kk + alc]);
                ldsm4(ah[mi][0], ah[mi][1], ah[mi][2], ah[mi][3], a0);
                uint32_t a1 = smaddr(&sm.Al[(mw * 32 + mi * 16 + alr) * AST + kk + alc]);
                ldsm4(al[mi][0], al[mi][1], al[mi][2], al[mi][3], a1);
            }
#pragma unroll
            for (int ni = 0; ni < 4; ni++) {
                uint32_t b0 = smaddr(&sm.Bh[(nw * 32 + ni * 8 + bl8) * BST + kk + bc8]);
                ldsm2(bh[ni][0], bh[ni][1], b0);
                uint32_t b1 = smaddr(&sm.Bl[(nw * 32 + ni * 8 + bl8) * BST + kk + bc8]);
                ldsm2(bl[ni][0], bl[ni][1], b1);
            }
#pragma unroll
            for (int mi = 0; mi < 2; mi++)
#pragma unroll
                for (int ni = 0; ni < 4; ni++) {
                    mma_bf16(acc[mi][ni], ah[mi], bh[ni]);
                    mma_bf16(acc[mi][ni], ah[mi], bl[ni]);
                    mma_bf16(acc[mi][ni], al[mi], bh[ni]);
                }
        }
        __syncthreads();
    }

    // epilogue: + D*x, direct stores
#pragma unroll
    for (int mi = 0; mi < 2; mi++)
#pragma unroll
        for (int ni = 0; ni < 4; ni++)
#pragma unroll
            for (int cp = 0; cp < 2; cp++) {
                int r = rowBase + mw * 32 + mi * 16 + (lane >> 2) + 8 * cp;
                int c = colBase + nw * 32 + ni * 8 + 2 * (lane & 3);
                float2 xv = *(const float2*)&x[(size_t)r * 256 + c];
                float2 dv = *(const float2*)&Dv[c];
                float2 o;
                o.x = acc[mi][ni][2 * cp + 0] + dv.x * xv.x;
                o.y = acc[mi][ni][2 * cp + 1] + dv.y * xv.y;
                *(float2*)&out[(size_t)r * 256 + c] = o;
            }
}

// ---------------- launch ----------------------------------------------------
extern "C" void kernel_launch(void* const* d_in, const int* in_sizes, int n_in,
                              void* d_out, int out_size)
{
    const float* x         = (const float*)d_in[0];
    const float* nu_log    = (const float*)d_in[1];
    const float* theta_log = (const float*)d_in[2];
    const float* B_re      = (const float*)d_in[3];
    const float* B_im      = (const float*)d_in[4];
    const float* C_re      = (const float*)d_in[5];
    const float* C_im      = (const float*)d_in[6];
    const float* Dv        = (const float*)d_in[7];
    const float* gamma_log = (const float*)d_in[8];
    float* out = (float*)d_out;

    k_setup<<<1, 256>>>(nu_log, theta_log, gamma_log);
    k_pack<<<768, 256>>>(B_re, B_im, C_re, C_im);
    k_gemm1<<<dim3(8, 1024), 256>>>(x);
    k_carry<<<256, 512>>>();
    k_gemm2<<<dim3(4, 1024), 256>>>(x, Dv, out);
}

// round 5
// speedup vs baseline: 2.2234x; 1.3593x over previous
#include <cuda_runtime.h>
#include <cuda_bf16.h>
#include <cstdint>

// Problem constants
#define L_DIM 131072
#define CSZ   128               // rows per CTA tile == scan chunk
#define NCH   (L_DIM / CSZ)     // 1024 chunks

// smem: 2 stages x 64KB (Ahi 16K | Alo 16K | Bhi 16K | Blo 16K)
#define STAGE_BYTES 65536
#define SMEM_TOTAL  131072
#define ZST 136
#define SEG_OFF 102400

// ---------------- static device scratch ------------------------------------
// State planes: [l][512] cols ordered per 128-col tile t: [re ch(64t..64t+63) | im same]
__device__ __nv_bfloat16 g_Shi[(size_t)L_DIM * 512];
__device__ __nv_bfloat16 g_Slo[(size_t)L_DIM * 512];
__device__ float g_gamma[256];
__device__ float g_pow_re[129 * 256];     // Lambda^p per channel (unpermuted)
__device__ float g_pow_im[129 * 256];
__device__ float g_cpow_re[10 * 256];     // Lambda^(128*2^d)
__device__ float g_cpow_im[10 * 256];
__device__ float g_qr[129 * 512];         // permuted correction tables
__device__ float g_qi[129 * 512];
__device__ float2 g_ccar[NCH * 256];      // chunk-end local states
__device__ float g_carP_re[NCH * 512];    // permuted duplicated carry-in
__device__ float g_carP_im[NCH * 512];
__device__ __nv_bfloat16 g_B2hi[512 * 256];   // B rows: tile t -> [re ch 64t..+63 | im same], x gamma
__device__ __nv_bfloat16 g_B2lo[512 * 256];
__device__ __nv_bfloat16 g_C2hi[256 * 512];   // C rows h, cols = permuted k (Cre / -Cim)
__device__ __nv_bfloat16 g_C2lo[256 * 512];

// ---------------- helpers ---------------------------------------------------
__device__ __forceinline__ uint32_t smem_u32(const void* p) {
    return (uint32_t)__cvta_generic_to_shared(p);
}
__device__ __forceinline__ void ldsm4(uint32_t& r0, uint32_t& r1, uint32_t& r2, uint32_t& r3, uint32_t a) {
    asm volatile("ldmatrix.sync.aligned.m8n8.x4.shared.b16 {%0,%1,%2,%3}, [%4];"
                 : "=r"(r0), "=r"(r1), "=r"(r2), "=r"(r3) : "r"(a));
}
__device__ __forceinline__ void mma_bf16(float* c, const uint32_t* a, const uint32_t* b) {
    asm volatile("mma.sync.aligned.m16n8k16.row.col.f32.bf16.bf16.f32 "
                 "{%0,%1,%2,%3},{%4,%5,%6,%7},{%8,%9},{%0,%1,%2,%3};"
                 : "+f"(c[0]), "+f"(c[1]), "+f"(c[2]), "+f"(c[3])
                 : "r"(a[0]), "r"(a[1]), "r"(a[2]), "r"(a[3]), "r"(b[0]), "r"(b[1]));
}
__device__ __forceinline__ float bf2f(unsigned short u) {
    return __bfloat162float(__ushort_as_bfloat16(u));
}
__device__ __forceinline__ void split2(float v, __nv_bfloat16& h, __nv_bfloat16& l) {
    h = __float2bfloat16(v);
    l = __float2bfloat16(v - __bfloat162float(h));
}
__device__ __forceinline__ uint32_t pack_hi2(float a, float b) {
    __nv_bfloat16 ha = __float2bfloat16(a), hb = __float2bfloat16(b);
    return (uint32_t)__bfloat16_as_ushort(ha) | ((uint32_t)__bfloat16_as_ushort(hb) << 16);
}
__device__ __forceinline__ uint32_t pack_lo2(float a, float b) {
    __nv_bfloat16 ha = __float2bfloat16(a), hb = __float2bfloat16(b);
    __nv_bfloat16 la = __float2bfloat16(a - __bfloat162float(ha));
    __nv_bfloat16 lb = __float2bfloat16(b - __bfloat162float(hb));
    return (uint32_t)__bfloat16_as_ushort(la) | ((uint32_t)__bfloat16_as_ushort(lb) << 16);
}

// ---------------- K0: parameters + tables -----------------------------------
__global__ void k_setup(const float* __restrict__ nu_log,
                        const float* __restrict__ theta_log,
                        const float* __restrict__ gamma_log)
{
    int n = threadIdx.x;
    double nu  = exp((double)nu_log[n]);
    double th  = exp((double)theta_log[n]);
    double mag = exp(-nu);
    double lr  = mag * cos(th);
    double li  = mag * sin(th);
    g_gamma[n] = expf(gamma_log[n]);
    int colre = ((n >> 6) << 7) + (n & 63);
    int colim = colre + 64;
    double pr = 1.0, pi = 0.0, cr = 1.0, ci = 0.0;
    for (int p = 0; p <= 128; p++) {
        g_pow_re[p * 256 + n] = (float)pr;
        g_pow_im[p * 256 + n] = (float)pi;
        g_qr[p * 512 + colre] = (float)pr;
        g_qi[p * 512 + colre] = (float)(-pi);
        g_qr[p * 512 + colim] = (float)pi;
        g_qi[p * 512 + colim] = (float)pr;
        if (p == 128) { cr = pr; ci = pi; }
        double t = pr * lr - pi * li;
        pi = pr * li + pi * lr;
        pr = t;
    }
    for (int d = 0; d < 10; d++) {
        g_cpow_re[d * 256 + n] = (float)cr;
        g_cpow_im[d * 256 + n] = (float)ci;
        double t = cr * cr - ci * ci;
        ci = 2.0 * cr * ci;
        cr = t;
    }
}

// ---------------- K0b: pack B and C bf16 hi/lo planes ------------------------
__global__ void k_pack(const float* __restrict__ Bre, const float* __restrict__ Bim,
                       const float* __restrict__ Cre, const float* __restrict__ Cim)
{
    int b = blockIdx.x;
    int t = threadIdx.x;
    if (b < 512) {
        int tile = b >> 7, loc = b & 127;
        int isim = loc >> 6;
        int ch = tile * 64 + (loc & 63);
        const float* src = isim ? Bim : Bre;
        float v = src[ch * 256 + t] * g_gamma[ch];
        __nv_bfloat16 h, l; split2(v, h, l);
        g_B2hi[b * 256 + t] = h;
        g_B2lo[b * 256 + t] = l;
    } else {
        int h = b - 512;
        for (int k = t; k < 512; k += 256) {
            int tile = k >> 7, loc = k & 127;
            int isim = loc >> 6;
            int ch = tile * 64 + (loc & 63);
            float v = isim ? -Cim[h * 256 + ch] : Cre[h * 256 + ch];
            __nv_bfloat16 hh, ll; split2(v, hh, ll);
            g_C2hi[h * 512 + k] = hh;
            g_C2lo[h * 512 + k] = ll;
        }
    }
}

// ---------------- shared MMA stage (BM=128, BN=128, BK=64) -------------------
// stage layout: Ahi @0, Alo @16384, Bhi @32768, Blo @49152
__device__ __forceinline__ void mma_stage(const char* base, float (*acc)[4],
                                          int lane, int warpm, int warpn)
{
    const int arow = warpm * 16 + (lane & 15);
    const int half = lane >> 4;
#pragma unroll
    for (int ks = 0; ks < 4; ks++) {
        int colA = (ks * 2 + half) ^ (arow & 7);
        uint32_t aAddr = smem_u32(base + arow * 128 + (colA << 4));
        uint32_t ah[4], al[4];
        ldsm4(ah[0], ah[1], ah[2], ah[3], aAddr);
        ldsm4(al[0], al[1], al[2], al[3], aAddr + 16384);
#pragma unroll
        for (int nj = 0; nj < 4; nj++) {
            int brow = warpn * 64 + nj * 16 + (lane & 15);
            int colB = (ks * 2 + half) ^ (brow & 7);
            uint32_t bAddr = smem_u32(base + 32768 + brow * 128 + (colB << 4));
            uint32_t bh[4], bl[4];
            ldsm4(bh[0], bh[1], bh[2], bh[3], bAddr);
            ldsm4(bl[0], bl[1], bl[2], bl[3], bAddr + 16384);
            uint32_t p0[2] = {bh[0], bh[2]}, p1[2] = {bh[1], bh[3]};
            uint32_t q0[2] = {bl[0], bl[2]}, q1[2] = {bl[1], bl[3]};
            mma_bf16(acc[2 * nj],     ah, p0);
            mma_bf16(acc[2 * nj + 1], ah, p1);
            mma_bf16(acc[2 * nj],     ah, q0);
            mma_bf16(acc[2 * nj + 1], ah, q1);
            mma_bf16(acc[2 * nj],     al, p0);
            mma_bf16(acc[2 * nj + 1], al, p1);
        }
    }
}

// ---------------- K1: Bu GEMM + fused local scan -----------------------------
__global__ __launch_bounds__(512, 1) void k_gemm1(const float* __restrict__ x)
{
    extern __shared__ char smem[];
    const int tid  = threadIdx.x;
    const int lane = tid & 31;
    const int warp = tid >> 5;
    const int warpm = warp >> 1;        // 0..7 -> 16-row slice
    const int warpn = warp & 1;         // 0..1 -> 64-col slice
    const int bx = blockIdx.x;          // 0..3 (128-col tile of 512)
    const int by = blockIdx.y;          // chunk
    const int rowBase = by * CSZ;

    float acc[8][4];
#pragma unroll
    for (int i = 0; i < 8; i++)
#pragma unroll
        for (int j = 0; j < 4; j++) acc[i][j] = 0.f;

    const int rowb = tid >> 4;          // 0..31
    const int c4   = tid & 15;          // col group (4 floats)
    const int browB = tid >> 3;         // 0..63 per half-pass
    const int uB    = tid & 7;

    float4 aR[4];
    uint4  bR[4];

    auto ldA = [&](int c) {
        int k0 = c * 64;
#pragma unroll
        for (int q = 0; q < 4; q++) {
            int r = rowb + 32 * q;
            aR[q] = *(const float4*)(x + (size_t)(rowBase + r) * 256 + k0 + c4 * 4);
        }
    };
    auto ldB = [&](int c) {
        int k0 = c * 64;
#pragma unroll
        for (int i = 0; i < 4; i++) {
            int row = browB + 64 * (i & 1);           // 0..127
            const __nv_bfloat16* src = (i < 2) ? g_B2hi : g_B2lo;
            bR[i] = *(const uint4*)(src + (size_t)(bx * 128 + row) * 256 + k0 + uB * 8);
        }
    };
    auto stA = [&](int s) {
        char* ah = smem + s * STAGE_BYTES;
#pragma unroll
        for (int q = 0; q < 4; q++) {
            int r = rowb + 32 * q;
            int col16 = (c4 >> 1) ^ (r & 7);
            uint32_t off = r * 128 + (col16 << 4) + (c4 & 1) * 8;
            uint2 hh = make_uint2(pack_hi2(aR[q].x, aR[q].y), pack_hi2(aR[q].z, aR[q].w));
            uint2 ll = make_uint2(pack_lo2(aR[q].x, aR[q].y), pack_lo2(aR[q].z, aR[q].w));
            *(uint2*)(ah + off) = hh;
            *(uint2*)(ah + 16384 + off) = ll;
        }
    };
    auto stB = [&](int s) {
        char* bh = smem + s * STAGE_BYTES + 32768;
#pragma unroll
        for (int i = 0; i < 4; i++) {
            int row = browB + 64 * (i & 1);
            uint32_t off = row * 128 + (((uB) ^ (row & 7)) << 4);
            *(uint4*)(((i < 2) ? bh : bh + 16384) + off) = bR[i];
        }
    };

    ldA(0); ldB(0);
    const int NCC = 4;
    for (int c = 0; c < NCC; c++) {
        int s = c & 1;
        stA(s); stB(s);
        if (c + 1 < NCC) { ldA(c + 1); ldB(c + 1); }
        __syncthreads();
        mma_stage(smem + s * STAGE_BYTES, acc, lane, warpm, warpn);
    }
    __syncthreads();

    // ---- acc -> zs ----
    float* zs = (float*)smem;
#pragma unroll
    for (int ni = 0; ni < 8; ni++) {
        int r0 = warpm * 16 + (lane >> 2);
        int col = warpn * 64 + ni * 8 + (lane & 3) * 2;
        zs[r0 * ZST + col]           = acc[ni][0];
        zs[r0 * ZST + col + 1]       = acc[ni][1];
        zs[(r0 + 8) * ZST + col]     = acc[ni][2];
        zs[(r0 + 8) * ZST + col + 1] = acc[ni][3];
    }
    __syncthreads();

    // ---- fused local scan: 64 channels, 8 segments x 16 rows ----
    {
        const int ch  = tid & 63;
        const int seg = tid >> 6;
        const int chg = bx * 64 + ch;
        const float lr = g_pow_re[256 + chg], li = g_pow_im[256 + chg];

        // pass 1: local segment end
        float cr = 0.f, ci = 0.f;
#pragma unroll
        for (int i = 0; i < 16; i++) {
            int r = seg * 16 + i;
            float br = zs[r * ZST + ch];
            float bi = zs[r * ZST + 64 + ch];
            float t = fmaf(lr, cr, fmaf(-li, ci, br));
            ci      = fmaf(lr, ci, fmaf( li, cr, bi));
            cr = t;
        }
        float2* se = (float2*)(smem + SEG_OFF);
        se[seg * 64 + ch] = make_float2(cr, ci);
        __syncthreads();

        // carry-in for my segment
        const float p16r = g_pow_re[16 * 256 + chg], p16i = g_pow_im[16 * 256 + chg];
        float gr = 0.f, gi = 0.f;
        for (int j = 0; j < seg; j++) {
            float2 e = se[j * 64 + ch];
            float t = fmaf(p16r, gr, fmaf(-p16i, gi, e.x));
            gi      = fmaf(p16r, gi, fmaf( p16i, gr, e.y));
            gr = t;
        }

        // pass 2: full scan + store split planes
        float wr = gr, wi = gi;
#pragma unroll
        for (int i = 0; i < 16; i++) {
            int r = seg * 16 + i;
            float br = zs[r * ZST + ch];
            float bi = zs[r * ZST + 64 + ch];
            float t = fmaf(lr, wr, fmaf(-li, wi, br));
            wi      = fmaf(lr, wi, fmaf( li, wr, bi));
            wr = t;
            size_t off = (size_t)(rowBase + r) * 512 + bx * 128;
            __nv_bfloat16 h, l;
            split2(wr, h, l);
            g_Shi[off + ch] = h;  g_Slo[off + ch] = l;
            split2(wi, h, l);
            g_Shi[off + 64 + ch] = h;  g_Slo[off + 64 + ch] = l;
            if (seg == 7 && i == 15) g_ccar[by * 256 + chg] = make_float2(wr, wi);
        }
    }
}

// ---------------- K2: parallel carry scan -> permuted carP -------------------
__global__ __launch_bounds__(512) void k_carry()
{
    __shared__ float2 s[NCH];
    const int ch = blockIdx.x;
    const int t = threadIdx.x;
    s[t]       = g_ccar[t * 256 + ch];
    s[t + 512] = g_ccar[(t + 512) * 256 + ch];
    __syncthreads();
#pragma unroll
    for (int d = 0; d < 10; d++) {
        int st = 1 << d;
        float pr = g_cpow_re[d * 256 + ch];
        float pi = g_cpow_im[d * 256 + ch];
        int c0 = t, c1 = t + 512;
        float2 v0 = s[c0], v1 = s[c1];
        if (c0 >= st) {
            float2 w = s[c0 - st];
            v0.x = fmaf(pr, w.x, fmaf(-pi, w.y, v0.x));
            v0.y = fmaf(pr, w.y, fmaf( pi, w.x, v0.y));
        }
        {
            float2 w = s[c1 - st];
            v1.x = fmaf(pr, w.x, fmaf(-pi, w.y, v1.x));
            v1.y = fmaf(pr, w.y, fmaf( pi, w.x, v1.y));
        }
        __syncthreads();
        s[c0] = v0; s[c1] = v1;
        __syncthreads();
    }
    const int colre = ((ch >> 6) << 7) + (ch & 63);
    const int colim = colre + 64;
    float2 e0 = (t == 0) ? make_float2(0.f, 0.f) : s[t - 1];
    g_carP_re[t * 512 + colre] = e0.x;  g_carP_re[t * 512 + colim] = e0.x;
    g_carP_im[t * 512 + colre] = e0.y;  g_carP_im[t * 512 + colim] = e0.y;
    float2 e1 = s[t + 511];
    size_t o1 = (size_t)(t + 512) * 512;
    g_carP_re[o1 + colre] = e1.x;  g_carP_re[o1 + colim] = e1.x;
    g_carP_im[o1 + colre] = e1.y;  g_carP_im[o1 + colim] = e1.y;
}

// ---------------- K3: output GEMM, correction fused --------------------------
__global__ __launch_bounds__(512, 1) void k_gemm2(const float* __restrict__ x,
                                                  const float* __restrict__ Dv,
                                                  float* __restrict__ out)
{
    extern __shared__ char smem[];
    const int tid  = threadIdx.x;
    const int lane = tid & 31;
    const int warp = tid >> 5;
    const int warpm = warp >> 1;
    const int warpn = warp & 1;
    const int bx = blockIdx.x;          // 0..1 h tile
    const int by = blockIdx.y;          // chunk
    const int rowBase = by * CSZ;

    float acc[8][4];
#pragma unroll
    for (int i = 0; i < 8; i++)
#pragma unroll
        for (int j = 0; j < 4; j++) acc[i][j] = 0.f;

    const int rowb = tid >> 4;
    const int c4   = tid & 15;
    const int browB = tid >> 3;
    const int uB    = tid & 7;

    uint2  sh[4], sl[4];
    float4 qr[4], qi[4];
    float4 cre, cim;
    uint4  bR[4];

    auto ldA = [&](int c) {
        int gk = c * 64 + c4 * 4;
        cre = *(const float4*)&g_carP_re[(size_t)by * 512 + gk];
        cim = *(const float4*)&g_carP_im[(size_t)by * 512 + gk];
#pragma unroll
        for (int q = 0; q < 4; q++) {
            int r = rowb + 32 * q;
            size_t l = (size_t)(rowBase + r);
            sh[q] = *(const uint2*)&g_Shi[l * 512 + gk];
            sl[q] = *(const uint2*)&g_Slo[l * 512 + gk];
            qr[q] = *(const float4*)&g_qr[(r + 1) * 512 + gk];
            qi[q] = *(const float4*)&g_qi[(r + 1) * 512 + gk];
        }
    };
    auto stA = [&](int s) {
        char* ah = smem + s * STAGE_BYTES;
        const float* crp = (const float*)&cre;
        const float* cip = (const float*)&cim;
#pragma unroll
        for (int q = 0; q < 4; q++) {
            int r = rowb + 32 * q;
            const unsigned short* hp = (const unsigned short*)&sh[q];
            const unsigned short* lp = (const unsigned short*)&sl[q];
            const float* qrp = (const float*)&qr[q];
            const float* qip = (const float*)&qi[q];
            float v[4];
#pragma unroll
            for (int j = 0; j < 4; j++)
                v[j] = bf2f(hp[j]) + bf2f(lp[j]) + qrp[j] * crp[j] + qip[j] * cip[j];
            int col16 = (c4 >> 1) ^ (r & 7);
            uint32_t off = r * 128 + (col16 << 4) + (c4 & 1) * 8;
            uint2 hh = make_uint2(pack_hi2(v[0], v[1]), pack_hi2(v[2], v[3]));
            uint2 ll = make_uint2(pack_lo2(v[0], v[1]), pack_lo2(v[2], v[3]));
            *(uint2*)(ah + off) = hh;
            *(uint2*)(ah + 16384 + off) = ll;
        }
    };
    auto ldB = [&](int c) {
        int k0 = c * 64;
#pragma unroll
        for (int i = 0; i < 4; i++) {
            int row = browB + 64 * (i & 1);
            const __nv_bfloat16* src = (i < 2) ? g_C2hi : g_C2lo;
            bR[i] = *(const uint4*)(src + (size_t)(bx * 128 + row) * 512 + k0 + uB * 8);
        }
    };
    auto stB = [&](int s) {
        char* bh = smem + s * STAGE_BYTES + 32768;
#pragma unroll
        for (int i = 0; i < 4; i++) {
            int row = browB + 64 * (i & 1);
            uint32_t off = row * 128 + (((uB) ^ (row & 7)) << 4);
            *(uint4*)(((i < 2) ? bh : bh + 16384) + off) = bR[i];
        }
    };

    ldA(0); ldB(0);
    const int NCC = 8;
    for (int c = 0; c < NCC; c++) {
        int s = c & 1;
        stA(s); stB(s);
        if (c + 1 < NCC) { ldA(c + 1); ldB(c + 1); }
        __syncthreads();
        mma_stage(smem + s * STAGE_BYTES, acc, lane, warpm, warpn);
    }
    __syncthreads();

    // ---- acc -> zs ----
    float* zs = (float*)smem;
#pragma unroll
    for (int ni = 0; ni < 8; ni++) {
        int r0 = warpm * 16 + (lane >> 2);
        int col = warpn * 64 + ni * 8 + (lane & 3) * 2;
        zs[r0 * ZST + col]           = acc[ni][0];
        zs[r0 * ZST + col + 1]       = acc[ni][1];
        zs[(r0 + 8) * ZST + col]     = acc[ni][2];
        zs[(r0 + 8) * ZST + col + 1] = acc[ni][3];
    }
    __syncthreads();

    // ---- epilogue: y = zs + D*x ----
    {
        int col = (tid & 31) * 4;
        int gh = bx * 128 + col;
        float4 dv = *(const float4*)&Dv[gh];
#pragma unroll
        for (int i = 0; i < 8; i++) {
            int r = (tid >> 5) + 16 * i;
            size_t l = (size_t)(rowBase + r);
            float4 xv = *(const float4*)&x[l * 256 + gh];
            float4 o;
            o.x = zs[r * ZST + col + 0] + dv.x * xv.x;
            o.y = zs[r * ZST + col + 1] + dv.y * xv.y;
            o.z = zs[r * ZST + col + 2] + dv.z * xv.z;
            o.w = zs[r * ZST + col + 3] + dv.w * xv.w;
            *(float4*)(out + l * 256 + gh) = o;
        }
    }
}

// ---------------- launch ----------------------------------------------------
extern "C" void kernel_launch(void* const* d_in, const int* in_sizes, int n_in,
                              void* d_out, int out_size)
{
    const float* x         = (const float*)d_in[0];
    const float* nu_log    = (const float*)d_in[1];
    const float* theta_log = (const float*)d_in[2];
    const float* B_re      = (const float*)d_in[3];
    const float* B_im      = (const float*)d_in[4];
    const float* C_re      = (const float*)d_in[5];
    const float* C_im      = (const float*)d_in[6];
    const float* Dv        = (const float*)d_in[7];
    const float* gamma_log = (const float*)d_in[8];
    float* out = (float*)d_out;

    cudaFuncSetAttribute(k_gemm1, cudaFuncAttributeMaxDynamicSharedMemorySize, SMEM_TOTAL);
    cudaFuncSetAttribute(k_gemm2, cudaFuncAttributeMaxDynamicSharedMemorySize, SMEM_TOTAL);

    k_setup<<<1, 256>>>(nu_log, theta_log, gamma_log);
    k_pack<<<768, 256>>>(B_re, B_im, C_re, C_im);
    k_gemm1<<<dim3(4, 1024), 512, SMEM_TOTAL>>>(x);
    k_carry<<<256, 512>>>();
    k_gemm2<<<dim3(2, 1024), 512, SMEM_TOTAL>>>(x, Dv, out);
}

// round 10
// speedup vs baseline: 2.5264x; 1.1363x over previous
#include <cuda_runtime.h>
#include <cuda_bf16.h>
#include <cstdint>

#define L_DIM 131072
#define CSZ   128
#define NCH   (L_DIM / CSZ)     // 1024

// stage: Ahi 16K | Alo 16K | Bhi 16K | Blo 16K
#define STAGE_BYTES 65536
#define SMEM_TOTAL  131072
#define ZST 136
#define SEG_OFF 102400

// ---------------- static device scratch ------------------------------------
__device__ float g_S[(size_t)L_DIM * 512];            // fp32 local-scan states (permuted cols)
__device__ __nv_bfloat16 g_Shi[(size_t)L_DIM * 512];  // corrected split planes
__device__ __nv_bfloat16 g_Slo[(size_t)L_DIM * 512];
__device__ __nv_bfloat16 g_xhi[(size_t)L_DIM * 256];  // pre-split x
__device__ __nv_bfloat16 g_xlo[(size_t)L_DIM * 256];
__device__ float g_gamma[256];
__device__ float g_pow_re[129 * 256];
__device__ float g_pow_im[129 * 256];
__device__ float g_cpow_re[10 * 256];
__device__ float g_cpow_im[10 * 256];
__device__ float g_qr[129 * 512];                     // permuted correction tables
__device__ float g_qi[129 * 512];
__device__ float2 g_ccar[NCH * 256];
__device__ float g_carP_re[NCH * 512];
__device__ float g_carP_im[NCH * 512];
__device__ __nv_bfloat16 g_B2hi[512 * 256];
__device__ __nv_bfloat16 g_B2lo[512 * 256];
__device__ __nv_bfloat16 g_C2hi[256 * 512];
__device__ __nv_bfloat16 g_C2lo[256 * 512];

// ---------------- helpers ---------------------------------------------------
__device__ __forceinline__ uint32_t smem_u32(const void* p) {
    return (uint32_t)__cvta_generic_to_shared(p);
}
__device__ __forceinline__ void ldsm4(uint32_t& r0, uint32_t& r1, uint32_t& r2, uint32_t& r3, uint32_t a) {
    asm volatile("ldmatrix.sync.aligned.m8n8.x4.shared.b16 {%0,%1,%2,%3}, [%4];"
                 : "=r"(r0), "=r"(r1), "=r"(r2), "=r"(r3) : "r"(a));
}
__device__ __forceinline__ void mma_bf16(float* c, const uint32_t* a, const uint32_t* b) {
    asm volatile("mma.sync.aligned.m16n8k16.row.col.f32.bf16.bf16.f32 "
                 "{%0,%1,%2,%3},{%4,%5,%6,%7},{%8,%9},{%0,%1,%2,%3};"
                 : "+f"(c[0]), "+f"(c[1]), "+f"(c[2]), "+f"(c[3])
                 : "r"(a[0]), "r"(a[1]), "r"(a[2]), "r"(a[3]), "r"(b[0]), "r"(b[1]));
}
#define CP_ASYNC(dst, src) asm volatile("cp.async.cg.shared.global [%0], [%1], 16;" :: "r"(dst), "l"(src))
#define CP_COMMIT()        asm volatile("cp.async.commit_group;" ::: "memory")
#define CP_WAIT0()         asm volatile("cp.async.wait_group 0;" ::: "memory")

__device__ __forceinline__ void split2(float v, __nv_bfloat16& h, __nv_bfloat16& l) {
    h = __float2bfloat16(v);
    l = __float2bfloat16(v - __bfloat162float(h));
}
__device__ __forceinline__ uint32_t pack_hi2(float a, float b) {
    __nv_bfloat16 ha = __float2bfloat16(a), hb = __float2bfloat16(b);
    return (uint32_t)__bfloat16_as_ushort(ha) | ((uint32_t)__bfloat16_as_ushort(hb) << 16);
}
__device__ __forceinline__ uint32_t pack_lo2(float a, float b) {
    __nv_bfloat16 ha = __float2bfloat16(a), hb = __float2bfloat16(b);
    __nv_bfloat16 la = __float2bfloat16(a - __bfloat162float(ha));
    __nv_bfloat16 lb = __float2bfloat16(b - __bfloat162float(hb));
    return (uint32_t)__bfloat16_as_ushort(la) | ((uint32_t)__bfloat16_as_ushort(lb) << 16);
}

// ---------------- K0: parameters + tables -----------------------------------
__global__ void k_setup(const float* __restrict__ nu_log,
                        const float* __restrict__ theta_log,
                        const float* __restrict__ gamma_log)
{
    int n = threadIdx.x;
    double nu  = exp((double)nu_log[n]);
    double th  = exp((double)theta_log[n]);
    double mag = exp(-nu);
    double lr  = mag * cos(th);
    double li  = mag * sin(th);
    g_gamma[n] = expf(gamma_log[n]);
    int colre = ((n >> 6) << 7) + (n & 63);
    int colim = colre + 64;
    double pr = 1.0, pi = 0.0, cr = 1.0, ci = 0.0;
    for (int p = 0; p <= 128; p++) {
        g_pow_re[p * 256 + n] = (float)pr;
        g_pow_im[p * 256 + n] = (float)pi;
        g_qr[p * 512 + colre] = (float)pr;
        g_qi[p * 512 + colre] = (float)(-pi);
        g_qr[p * 512 + colim] = (float)pi;
        g_qi[p * 512 + colim] = (float)pr;
        if (p == 128) { cr = pr; ci = pi; }
        double t = pr * lr - pi * li;
        pi = pr * li + pi * lr;
        pr = t;
    }
    for (int d = 0; d < 10; d++) {
        g_cpow_re[d * 256 + n] = (float)cr;
        g_cpow_im[d * 256 + n] = (float)ci;
        double t = cr * cr - ci * ci;
        ci = 2.0 * cr * ci;
        cr = t;
    }
}

// ---------------- K0b: pack B and C -----------------------------------------
__global__ void k_pack(const float* __restrict__ Bre, const float* __restrict__ Bim,
                       const float* __restrict__ Cre, const float* __restrict__ Cim)
{
    int b = blockIdx.x;
    int t = threadIdx.x;
    if (b < 512) {
        int tile = b >> 7, loc = b & 127;
        int isim = loc >> 6;
        int ch = tile * 64 + (loc & 63);
        const float* src = isim ? Bim : Bre;
        float v = src[ch * 256 + t] * g_gamma[ch];
        __nv_bfloat16 h, l; split2(v, h, l);
        g_B2hi[b * 256 + t] = h;
        g_B2lo[b * 256 + t] = l;
    } else {
        int h = b - 512;
        for (int k = t; k < 512; k += 256) {
            int tile = k >> 7, loc = k & 127;
            int isim = loc >> 6;
            int ch = tile * 64 + (loc & 63);
            float v = isim ? -Cim[h * 256 + ch] : Cre[h * 256 + ch];
            __nv_bfloat16 hh, ll; split2(v, hh, ll);
            g_C2hi[h * 512 + k] = hh;
            g_C2lo[h * 512 + k] = ll;
        }
    }
}

// ---------------- K0c: pre-split x ------------------------------------------
__global__ __launch_bounds__(256) void k_prex(const float* __restrict__ x)
{
    size_t idx = ((size_t)blockIdx.x * 256 + threadIdx.x) * 4;
    float4 v = *(const float4*)(x + idx);
    uint2 hh = make_uint2(pack_hi2(v.x, v.y), pack_hi2(v.z, v.w));
    uint2 ll = make_uint2(pack_lo2(v.x, v.y), pack_lo2(v.z, v.w));
    *(uint2*)&g_xhi[idx] = hh;
    *(uint2*)&g_xlo[idx] = ll;
}

// ---------------- shared MMA stage: 32x32 warp tiles, BM=128, BN=128, BK=64 --
__device__ __forceinline__ void mma_stage(const char* base, float (*acc)[4][4],
                                          int lane, int warpm, int warpn)
{
    const int half = lane >> 4;
#pragma unroll
    for (int ks = 0; ks < 4; ks++) {
        uint32_t ah[2][4], al[2][4], bh[2][4], bl[2][4];
#pragma unroll
        for (int mi = 0; mi < 2; mi++) {
            int arow = warpm * 32 + mi * 16 + (lane & 15);
            int colA = (ks * 2 + half) ^ (arow & 7);
            uint32_t aAddr = smem_u32(base + arow * 128 + (colA << 4));
            ldsm4(ah[mi][0], ah[mi][1], ah[mi][2], ah[mi][3], aAddr);
            ldsm4(al[mi][0], al[mi][1], al[mi][2], al[mi][3], aAddr + 16384);
        }
#pragma unroll
        for (int nb = 0; nb < 2; nb++) {
            int brow = warpn * 32 + nb * 16 + (lane & 15);
            int colB = (ks * 2 + half) ^ (brow & 7);
            uint32_t bAddr = smem_u32(base + 32768 + brow * 128 + (colB << 4));
            ldsm4(bh[nb][0], bh[nb][1], bh[nb][2], bh[nb][3], bAddr);
            ldsm4(bl[nb][0], bl[nb][1], bl[nb][2], bl[nb][3], bAddr + 16384);
        }
#pragma unroll
        for (int mi = 0; mi < 2; mi++)
#pragma unroll
            for (int nb = 0; nb < 2; nb++) {
                uint32_t p0[2] = {bh[nb][0], bh[nb][2]}, p1[2] = {bh[nb][1], bh[nb][3]};
                uint32_t q0[2] = {bl[nb][0], bl[nb][2]}, q1[2] = {bl[nb][1], bl[nb][3]};
                mma_bf16(acc[mi][2 * nb],     ah[mi], p0);
                mma_bf16(acc[mi][2 * nb + 1], ah[mi], p1);
                mma_bf16(acc[mi][2 * nb],     ah[mi], q0);
                mma_bf16(acc[mi][2 * nb + 1], ah[mi], q1);
                mma_bf16(acc[mi][2 * nb],     al[mi], p0);
                mma_bf16(acc[mi][2 * nb + 1], al[mi], p1);
            }
    }
}

__device__ __forceinline__ void acc_to_zs(float* zs, float (*acc)[4][4],
                                          int lane, int warpm, int warpn)
{
#pragma unroll
    for (int mi = 0; mi < 2; mi++)
#pragma unroll
        for (int ni = 0; ni < 4; ni++) {
            int r0 = warpm * 32 + mi * 16 + (lane >> 2);
            int col = warpn * 32 + ni * 8 + (lane & 3) * 2;
            zs[r0 * ZST + col]           = acc[mi][ni][0];
            zs[r0 * ZST + col + 1]       = acc[mi][ni][1];
            zs[(r0 + 8) * ZST + col]     = acc[mi][ni][2];
            zs[(r0 + 8) * ZST + col + 1] = acc[mi][ni][3];
        }
}

// ---------------- K1: Bu GEMM (cp.async) + fused local scan ------------------
__global__ __launch_bounds__(512, 1) void k_gemm1()
{
    extern __shared__ __align__(1024) char smem[];
    const int tid  = threadIdx.x;
    const int lane = tid & 31;
    const int warp = tid >> 5;
    const int warpm = warp & 3;
    const int warpn = warp >> 2;
    const int bx = blockIdx.x;          // 0..3 N-tile
    const int by = blockIdx.y;          // chunk
    const int rowBase = by * CSZ;
    const uint32_t sm0 = smem_u32(smem);

    float acc[2][4][4];
#pragma unroll
    for (int mi = 0; mi < 2; mi++)
#pragma unroll
        for (int ni = 0; ni < 4; ni++)
#pragma unroll
            for (int j = 0; j < 4; j++) acc[mi][ni][j] = 0.f;

    auto issue = [&](int c) {
        int s = c & 1;
        uint32_t sb = sm0 + s * STAGE_BYTES;
        int k0 = c * 64;
#pragma unroll
        for (int p = 0; p < 2; p++) {
            int id = tid + 512 * p;
            int r = id >> 3, u = id & 7;
            uint32_t off = r * 128 + ((u ^ (r & 7)) << 4);
            const __nv_bfloat16* a0 = g_xhi + (size_t)(rowBase + r) * 256 + k0 + u * 8;
            const __nv_bfloat16* a1 = g_xlo + (size_t)(rowBase + r) * 256 + k0 + u * 8;
            const __nv_bfloat16* b0 = g_B2hi + (size_t)(bx * 128 + r) * 256 + k0 + u * 8;
            const __nv_bfloat16* b1 = g_B2lo + (size_t)(bx * 128 + r) * 256 + k0 + u * 8;
            CP_ASYNC(sb + off,          a0);
            CP_ASYNC(sb + 16384 + off,  a1);
            CP_ASYNC(sb + 32768 + off,  b0);
            CP_ASYNC(sb + 49152 + off,  b1);
        }
        CP_COMMIT();
    };

    issue(0);
    const int NCC = 4;
    for (int c = 0; c < NCC; c++) {
        CP_WAIT0();
        __syncthreads();
        if (c + 1 < NCC) issue(c + 1);
        mma_stage(smem + (c & 1) * STAGE_BYTES, acc, lane, warpm, warpn);
    }
    __syncthreads();

    float* zs = (float*)smem;
    acc_to_zs(zs, acc, lane, warpm, warpn);
    __syncthreads();

    // fused local scan: 64 channels x 8 segments x 16 rows
    {
        const int ch  = tid & 63;
        const int seg = tid >> 6;
        const int chg = bx * 64 + ch;
        const float lr = g_pow_re[256 + chg], li = g_pow_im[256 + chg];

        float cr = 0.f, ci = 0.f;
#pragma unroll
        for (int i = 0; i < 16; i++) {
            int r = seg * 16 + i;
            float br = zs[r * ZST + ch];
            float bi = zs[r * ZST + 64 + ch];
            float t = fmaf(lr, cr, fmaf(-li, ci, br));
            ci      = fmaf(lr, ci, fmaf( li, cr, bi));
            cr = t;
        }
        float2* se = (float2*)(smem + SEG_OFF);
        se[seg * 64 + ch] = make_float2(cr, ci);
        __syncthreads();

        const float p16r = g_pow_re[16 * 256 + chg], p16i = g_pow_im[16 * 256 + chg];
        float gr = 0.f, gi = 0.f;
        for (int j = 0; j < seg; j++) {
            float2 e = se[j * 64 + ch];
            float t = fmaf(p16r, gr, fmaf(-p16i, gi, e.x));
            gi      = fmaf(p16r, gi, fmaf( p16i, gr, e.y));
            gr = t;
        }

        float wr = gr, wi = gi;
#pragma unroll
        for (int i = 0; i < 16; i++) {
            int r = seg * 16 + i;
            float br = zs[r * ZST + ch];
            float bi = zs[r * ZST + 64 + ch];
            float t = fmaf(lr, wr, fmaf(-li, wi, br));
            wi      = fmaf(lr, wi, fmaf( li, wr, bi));
            wr = t;
            size_t off = (size_t)(rowBase + r) * 512 + bx * 128;
            g_S[off + ch]      = wr;
            g_S[off + 64 + ch] = wi;
            if (seg == 7 && i == 15) g_ccar[by * 256 + chg] = make_float2(wr, wi);
        }
    }
}

// ---------------- K2: parallel carry scan ------------------------------------
__global__ __launch_bounds__(512) void k_carry()
{
    __shared__ float2 s[NCH];
    const int ch = blockIdx.x;
    const int t = threadIdx.x;
    s[t]       = g_ccar[t * 256 + ch];
    s[t + 512] = g_ccar[(t + 512) * 256 + ch];
    __syncthreads();
#pragma unroll
    for (int d = 0; d < 10; d++) {
        int st = 1 << d;
        float pr = g_cpow_re[d * 256 + ch];
        float pi = g_cpow_im[d * 256 + ch];
        int c0 = t, c1 = t + 512;
        float2 v0 = s[c0], v1 = s[c1];
        if (c0 >= st) {
            float2 w = s[c0 - st];
            v0.x = fmaf(pr, w.x, fmaf(-pi, w.y, v0.x));
            v0.y = fmaf(pr, w.y, fmaf( pi, w.x, v0.y));
        }
        {
            float2 w = s[c1 - st];
            v1.x = fmaf(pr, w.x, fmaf(-pi, w.y, v1.x));
            v1.y = fmaf(pr, w.y, fmaf( pi, w.x, v1.y));
        }
        __syncthreads();
        s[c0] = v0; s[c1] = v1;
        __syncthreads();
    }
    const int colre = ((ch >> 6) << 7) + (ch & 63);
    const int colim = colre + 64;
    float2 e0 = (t == 0) ? make_float2(0.f, 0.f) : s[t - 1];
    g_carP_re[t * 512 + colre] = e0.x;  g_carP_re[t * 512 + colim] = e0.x;
    g_carP_im[t * 512 + colre] = e0.y;  g_carP_im[t * 512 + colim] = e0.y;
    float2 e1 = s[t + 511];
    size_t o1 = (size_t)(t + 512) * 512;
    g_carP_re[o1 + colre] = e1.x;  g_carP_re[o1 + colim] = e1.x;
    g_carP_im[o1 + colre] = e1.y;  g_carP_im[o1 + colim] = e1.y;
}

// ---------------- K2b: correction + split pass -------------------------------
__global__ __launch_bounds__(512) void k_corr()
{
    const int chunk = blockIdx.x;
    const int tid = threadIdx.x;
    const int col = (tid & 255) * 2;
    const int rh  = tid >> 8;                 // 0 or 1 -> rows 0-63 / 64-127
    const int rowBase = chunk * CSZ;
    float2 cr = *(const float2*)&g_carP_re[(size_t)chunk * 512 + col];
    float2 ci = *(const float2*)&g_carP_im[(size_t)chunk * 512 + col];
#pragma unroll 4
    for (int i = 0; i < 64; i++) {
        int r = rh * 64 + i;
        size_t off = (size_t)(rowBase + r) * 512 + col;
        float2 s  = *(const float2*)&g_S[off];
        float2 qr = *(const float2*)&g_qr[(r + 1) * 512 + col];
        float2 qi = *(const float2*)&g_qi[(r + 1) * 512 + col];
        float v0 = s.x + qr.x * cr.x + qi.x * ci.x;
        float v1 = s.y + qr.y * cr.y + qi.y * ci.y;
        *(uint32_t*)&g_Shi[off] = pack_hi2(v0, v1);
        *(uint32_t*)&g_Slo[off] = pack_lo2(v0, v1);
    }
}

// ---------------- K3: output GEMM (cp.async) ---------------------------------
__global__ __launch_bounds__(512, 1) void k_gemm2(const float* __restrict__ x,
                                                  const float* __restrict__ Dv,
                                                  float* __restrict__ out)
{
    extern __shared__ __align__(1024) char smem[];
    const int tid  = threadIdx.x;
    const int lane = tid & 31;
    const int warp = tid >> 5;
    const int warpm = warp & 3;
    const int warpn = warp >> 2;
    const int bx = blockIdx.x;          // 0..1 h tile
    const int by = blockIdx.y;          // chunk
    const int rowBase = by * CSZ;
    const uint32_t sm0 = smem_u32(smem);

    float acc[2][4][4];
#pragma unroll
    for (int mi = 0; mi < 2; mi++)
#pragma unroll
        for (int ni = 0; ni < 4; ni++)
#pragma unroll
            for (int j = 0; j < 4; j++) acc[mi][ni][j] = 0.f;

    auto issue = [&](int c) {
        int s = c & 1;
        uint32_t sb = sm0 + s * STAGE_BYTES;
        int k0 = c * 64;
#pragma unroll
        for (int p = 0; p < 2; p++) {
            int id = tid + 512 * p;
            int r = id >> 3, u = id & 7;
            uint32_t off = r * 128 + ((u ^ (r & 7)) << 4);
            const __nv_bfloat16* a0 = g_Shi + (size_t)(rowBase + r) * 512 + k0 + u * 8;
            const __nv_bfloat16* a1 = g_Slo + (size_t)(rowBase + r) * 512 + k0 + u * 8;
            const __nv_bfloat16* b0 = g_C2hi + (size_t)(bx * 128 + r) * 512 + k0 + u * 8;
            const __nv_bfloat16* b1 = g_C2lo + (size_t)(bx * 128 + r) * 512 + k0 + u * 8;
            CP_ASYNC(sb + off,          a0);
            CP_ASYNC(sb + 16384 + off,  a1);
            CP_ASYNC(sb + 32768 + off,  b0);
            CP_ASYNC(sb + 49152 + off,  b1);
        }
        CP_COMMIT();
    };

    issue(0);
    const int NCC = 8;
    for (int c = 0; c < NCC; c++) {
        CP_WAIT0();
        __syncthreads();
        if (c + 1 < NCC) issue(c + 1);
        mma_stage(smem + (c & 1) * STAGE_BYTES, acc, lane, warpm, warpn);
    }
    __syncthreads();

    float* zs = (float*)smem;
    acc_to_zs(zs, acc, lane, warpm, warpn);
    __syncthreads();

    // epilogue: y = zs + D*x
    {
        int col = (tid & 31) * 4;
        int gh = bx * 128 + col;
        float4 dv = *(const float4*)&Dv[gh];
#pragma unroll
        for (int i = 0; i < 8; i++) {
            int r = (tid >> 5) + 16 * i;
            size_t l = (size_t)(rowBase + r);
            float4 xv = *(const float4*)&x[l * 256 + gh];
            float4 o;
            o.x = zs[r * ZST + col + 0] + dv.x * xv.x;
            o.y = zs[r * ZST + col + 1] + dv.y * xv.y;
            o.z = zs[r * ZST + col + 2] + dv.z * xv.z;
            o.w = zs[r * ZST + col + 3] + dv.w * xv.w;
            *(float4*)(out + l * 256 + gh) = o;
        }
    }
}

// ---------------- launch ----------------------------------------------------
extern "C" void kernel_launch(void* const* d_in, const int* in_sizes, int n_in,
                              void* d_out, int out_size)
{
    const float* x         = (const float*)d_in[0];
    const float* nu_log    = (const float*)d_in[1];
    const float* theta_log = (const float*)d_in[2];
    const float* B_re      = (const float*)d_in[3];
    const float* B_im      = (const float*)d_in[4];
    const float* C_re      = (const float*)d_in[5];
    const float* C_im      = (const float*)d_in[6];
    const float* Dv        = (const float*)d_in[7];
    const float* gamma_log = (const float*)d_in[8];
    float* out = (float*)d_out;

    cudaFuncSetAttribute(k_gemm1, cudaFuncAttributeMaxDynamicSharedMemorySize, SMEM_TOTAL);
    cudaFuncSetAttribute(k_gemm2, cudaFuncAttributeMaxDynamicSharedMemorySize, SMEM_TOTAL);

    k_setup<<<1, 256>>>(nu_log, theta_log, gamma_log);
    k_pack<<<768, 256>>>(B_re, B_im, C_re, C_im);
    k_prex<<<L_DIM * 256 / 1024, 256>>>(x);
    k_gemm1<<<dim3(4, 1024), 512, SMEM_TOTAL>>>();
    k_carry<<<256, 512>>>();
    k_corr<<<1024, 512>>>();
    k_gemm2<<<dim3(2, 1024), 512, SMEM_TOTAL>>>(x, Dv, out);
}

// round 11
// speedup vs baseline: 2.5719x; 1.0180x over previous
#include <cuda_runtime.h>
#include <cuda_bf16.h>
#include <cstdint>

#define L_DIM 131072
#define CSZ   128
#define NCH   (L_DIM / CSZ)     // 1024

// stage: Ahi 16K | Alo 16K | Bhi 32K | Blo 32K   (BM=128, BN=256, BK=64)
#define STAGE_BYTES 98304
#define SMEM_TOTAL  196608
#define ZST 264
#define SEG_OFF 135168

// ---------------- static device scratch ------------------------------------
__device__ float g_S[(size_t)L_DIM * 512];            // fp32 local-scan states (permuted cols)
__device__ __nv_bfloat16 g_Shi[(size_t)L_DIM * 512];  // corrected split planes
__device__ __nv_bfloat16 g_Slo[(size_t)L_DIM * 512];
__device__ __nv_bfloat16 g_xhi[(size_t)L_DIM * 256];  // pre-split x
__device__ __nv_bfloat16 g_xlo[(size_t)L_DIM * 256];
__device__ float g_gamma[256];
__device__ float g_pow_re[129 * 256];
__device__ float g_pow_im[129 * 256];
__device__ float g_cpow_re[10 * 256];
__device__ float g_cpow_im[10 * 256];
__device__ float g_qr[129 * 512];                     // permuted correction tables
__device__ float g_qi[129 * 512];
__device__ float2 g_ccar[NCH * 256];
__device__ float g_carP_re[NCH * 512];
__device__ float g_carP_im[NCH * 512];
__device__ __nv_bfloat16 g_B2hi[512 * 256];           // rows: grp g: [re ch 128g.. | im same]
__device__ __nv_bfloat16 g_B2lo[512 * 256];
__device__ __nv_bfloat16 g_C2hi[256 * 512];           // row h, permuted k cols
__device__ __nv_bfloat16 g_C2lo[256 * 512];

// ---------------- helpers ---------------------------------------------------
__device__ __forceinline__ uint32_t smem_u32(const void* p) {
    return (uint32_t)__cvta_generic_to_shared(p);
}
__device__ __forceinline__ void ldsm4(uint32_t& r0, uint32_t& r1, uint32_t& r2, uint32_t& r3, uint32_t a) {
    asm volatile("ldmatrix.sync.aligned.m8n8.x4.shared.b16 {%0,%1,%2,%3}, [%4];"
                 : "=r"(r0), "=r"(r1), "=r"(r2), "=r"(r3) : "r"(a));
}
__device__ __forceinline__ void mma_bf16(float* c, const uint32_t* a, const uint32_t* b) {
    asm volatile("mma.sync.aligned.m16n8k16.row.col.f32.bf16.bf16.f32 "
                 "{%0,%1,%2,%3},{%4,%5,%6,%7},{%8,%9},{%0,%1,%2,%3};"
                 : "+f"(c[0]), "+f"(c[1]), "+f"(c[2]), "+f"(c[3])
                 : "r"(a[0]), "r"(a[1]), "r"(a[2]), "r"(a[3]), "r"(b[0]), "r"(b[1]));
}
#define CP_ASYNC(dst, src) asm volatile("cp.async.cg.shared.global [%0], [%1], 16;" :: "r"(dst), "l"(src))
#define CP_COMMIT()        asm volatile("cp.async.commit_group;" ::: "memory")
#define CP_WAIT0()         asm volatile("cp.async.wait_group 0;" ::: "memory")

__device__ __forceinline__ void split2(float v, __nv_bfloat16& h, __nv_bfloat16& l) {
    h = __float2bfloat16(v);
    l = __float2bfloat16(v - __bfloat162float(h));
}
__device__ __forceinline__ uint32_t pack_hi2(float a, float b) {
    __nv_bfloat16 ha = __float2bfloat16(a), hb = __float2bfloat16(b);
    return (uint32_t)__bfloat16_as_ushort(ha) | ((uint32_t)__bfloat16_as_ushort(hb) << 16);
}
__device__ __forceinline__ uint32_t pack_lo2(float a, float b) {
    __nv_bfloat16 ha = __float2bfloat16(a), hb = __float2bfloat16(b);
    __nv_bfloat16 la = __float2bfloat16(a - __bfloat162float(ha));
    __nv_bfloat16 lb = __float2bfloat16(b - __bfloat162float(hb));
    return (uint32_t)__bfloat16_as_ushort(la) | ((uint32_t)__bfloat16_as_ushort(lb) << 16);
}

// ---------------- K0: parameters + tables (128-channel grouping) -------------
__global__ void k_setup(const float* __restrict__ nu_log,
                        const float* __restrict__ theta_log,
                        const float* __restrict__ gamma_log)
{
    int n = threadIdx.x;
    double nu  = exp((double)nu_log[n]);
    double th  = exp((double)theta_log[n]);
    double mag = exp(-nu);
    double lr  = mag * cos(th);
    double li  = mag * sin(th);
    g_gamma[n] = expf(gamma_log[n]);
    int colre = ((n >> 7) << 8) + (n & 127);
    int colim = colre + 128;
    double pr = 1.0, pi = 0.0, cr = 1.0, ci = 0.0;
    for (int p = 0; p <= 128; p++) {
        g_pow_re[p * 256 + n] = (float)pr;
        g_pow_im[p * 256 + n] = (float)pi;
        g_qr[p * 512 + colre] = (float)pr;
        g_qi[p * 512 + colre] = (float)(-pi);
        g_qr[p * 512 + colim] = (float)pi;
        g_qi[p * 512 + colim] = (float)pr;
        if (p == 128) { cr = pr; ci = pi; }
        double t = pr * lr - pi * li;
        pi = pr * li + pi * lr;
        pr = t;
    }
    for (int d = 0; d < 10; d++) {
        g_cpow_re[d * 256 + n] = (float)cr;
        g_cpow_im[d * 256 + n] = (float)ci;
        double t = cr * cr - ci * ci;
        ci = 2.0 * cr * ci;
        cr = t;
    }
}

// ---------------- K0b: pack B and C (128-channel grouping) -------------------
__global__ void k_pack(const float* __restrict__ Bre, const float* __restrict__ Bim,
                       const float* __restrict__ Cre, const float* __restrict__ Cim)
{
    int b = blockIdx.x;
    int t = threadIdx.x;
    if (b < 512) {
        int g = b >> 8, loc = b & 255;
        int isim = loc >> 7;
        int ch = g * 128 + (loc & 127);
        const float* src = isim ? Bim : Bre;
        float v = src[ch * 256 + t] * g_gamma[ch];
        __nv_bfloat16 h, l; split2(v, h, l);
        g_B2hi[b * 256 + t] = h;
        g_B2lo[b * 256 + t] = l;
    } else {
        int h = b - 512;
        for (int k = t; k < 512; k += 256) {
            int g = k >> 8, loc = k & 255;
            int isim = loc >> 7;
            int ch = g * 128 + (loc & 127);
            float v = isim ? -Cim[h * 256 + ch] : Cre[h * 256 + ch];
            __nv_bfloat16 hh, ll; split2(v, hh, ll);
            g_C2hi[h * 512 + k] = hh;
            g_C2lo[h * 512 + k] = ll;
        }
    }
}

// ---------------- K0c: pre-split x ------------------------------------------
__global__ __launch_bounds__(256) void k_prex(const float* __restrict__ x)
{
    size_t idx = ((size_t)blockIdx.x * 256 + threadIdx.x) * 4;
    float4 v = *(const float4*)(x + idx);
    uint2 hh = make_uint2(pack_hi2(v.x, v.y), pack_hi2(v.z, v.w));
    uint2 ll = make_uint2(pack_lo2(v.x, v.y), pack_lo2(v.z, v.w));
    *(uint2*)&g_xhi[idx] = hh;
    *(uint2*)&g_xlo[idx] = ll;
}

// ---------------- MMA stage: 64x32 warp tiles, BM=128 BN=256 BK=64 -----------
// layout: Ahi @0, Alo @16384, Bhi @32768, Blo @65536
__device__ __forceinline__ void mma_stage(const char* base, float (*acc)[4][4],
                                          int lane, int warpm, int warpn)
{
    const int half = lane >> 4;
    const int l15 = lane & 15;
#pragma unroll
    for (int ks = 0; ks < 4; ks++) {
        uint32_t bh[2][4], bl[2][4];
#pragma unroll
        for (int nb = 0; nb < 2; nb++) {
            int brow = warpn * 32 + nb * 16 + l15;
            int colB = (ks * 2 + half) ^ (brow & 7);
            uint32_t bAddr = smem_u32(base + 32768 + brow * 128 + (colB << 4));
            ldsm4(bh[nb][0], bh[nb][1], bh[nb][2], bh[nb][3], bAddr);
            ldsm4(bl[nb][0], bl[nb][1], bl[nb][2], bl[nb][3], bAddr + 32768);
        }
#pragma unroll
        for (int mi = 0; mi < 4; mi++) {
            int arow = warpm * 64 + mi * 16 + l15;
            int colA = (ks * 2 + half) ^ (arow & 7);
            uint32_t aAddr = smem_u32(base + arow * 128 + (colA << 4));
            uint32_t ah[4], al[4];
            ldsm4(ah[0], ah[1], ah[2], ah[3], aAddr);
            ldsm4(al[0], al[1], al[2], al[3], aAddr + 16384);
#pragma unroll
            for (int nb = 0; nb < 2; nb++) {
                uint32_t p0[2] = {bh[nb][0], bh[nb][2]}, p1[2] = {bh[nb][1], bh[nb][3]};
                uint32_t q0[2] = {bl[nb][0], bl[nb][2]}, q1[2] = {bl[nb][1], bl[nb][3]};
                mma_bf16(acc[mi][2 * nb],     ah, p0);
                mma_bf16(acc[mi][2 * nb + 1], ah, p1);
                mma_bf16(acc[mi][2 * nb],     ah, q0);
                mma_bf16(acc[mi][2 * nb + 1], ah, q1);
                mma_bf16(acc[mi][2 * nb],     al, p0);
                mma_bf16(acc[mi][2 * nb + 1], al, p1);
            }
        }
    }
}

__device__ __forceinline__ void acc_to_zs(float* zs, float (*acc)[4][4],
                                          int lane, int warpm, int warpn)
{
#pragma unroll
    for (int mi = 0; mi < 4; mi++)
#pragma unroll
        for (int ni = 0; ni < 4; ni++) {
            int r0 = warpm * 64 + mi * 16 + (lane >> 2);
            int col = warpn * 32 + ni * 8 + (lane & 3) * 2;
            zs[r0 * ZST + col]           = acc[mi][ni][0];
            zs[r0 * ZST + col + 1]       = acc[mi][ni][1];
            zs[(r0 + 8) * ZST + col]     = acc[mi][ni][2];
            zs[(r0 + 8) * ZST + col + 1] = acc[mi][ni][3];
        }
}

// ---------------- K1: Bu GEMM + fused local scan -----------------------------
__global__ __launch_bounds__(512, 1) void k_gemm1()
{
    extern __shared__ __align__(1024) char smem[];
    const int tid  = threadIdx.x;
    const int lane = tid & 31;
    const int warp = tid >> 5;
    const int warpm = warp & 1;         // 2 x 64 rows
    const int warpn = warp >> 1;        // 8 x 32 cols
    const int bx = blockIdx.x;          // 0..1 (128 complex channels each)
    const int by = blockIdx.y;
    const int rowBase = by * CSZ;
    const uint32_t sm0 = smem_u32(smem);

    float acc[4][4][4];
#pragma unroll
    for (int mi = 0; mi < 4; mi++)
#pragma unroll
        for (int ni = 0; ni < 4; ni++)
#pragma unroll
            for (int j = 0; j < 4; j++) acc[mi][ni][j] = 0.f;

    // A granule: 128 rows x 8 granules = 1024 per plane; 2 reps/thread/plane
    const int rA = tid >> 3;            // row for rep0 (rows 0..63), rep1 rows 64..127
    const int gA = tid & 7;
    const uint32_t offA = ((gA ^ (rA & 7)) << 4);
    // B granule: 256 rows x 8 = 2048 per plane; 4 reps/thread/plane
    auto issue = [&](int c) {
        uint32_t sb = sm0 + (c & 1) * STAGE_BYTES;
        int k0 = c * 64;
        const __nv_bfloat16* axh = g_xhi + (size_t)(rowBase + rA) * 256 + k0 + gA * 8;
        const __nv_bfloat16* axl = g_xlo + (size_t)(rowBase + rA) * 256 + k0 + gA * 8;
        uint32_t dA = sb + rA * 128 + offA;
        CP_ASYNC(dA, axh);
        CP_ASYNC(dA + 16384, axl);
        CP_ASYNC(dA + 64 * 128, axh + 64 * 256);
        CP_ASYNC(dA + 16384 + 64 * 128, axl + 64 * 256);
#pragma unroll
        for (int rep = 0; rep < 4; rep++) {
            int id = tid + 512 * rep;
            int r = id >> 3, g = id & 7;
            uint32_t off = r * 128 + ((g ^ (r & 7)) << 4);
            const __nv_bfloat16* b0 = g_B2hi + (size_t)(bx * 256 + r) * 256 + k0 + g * 8;
            const __nv_bfloat16* b1 = g_B2lo + (size_t)(bx * 256 + r) * 256 + k0 + g * 8;
            CP_ASYNC(sb + 32768 + off, b0);
            CP_ASYNC(sb + 65536 + off, b1);
        }
        CP_COMMIT();
    };

    issue(0);
    const int NCC = 4;
    for (int c = 0; c < NCC; c++) {
        CP_WAIT0();
        __syncthreads();
        if (c + 1 < NCC) issue(c + 1);
        mma_stage(smem + (c & 1) * STAGE_BYTES, acc, lane, warpm, warpn);
        if (c + 1 < NCC) __syncthreads();
    }
    __syncthreads();

    float* zs = (float*)smem;
    acc_to_zs(zs, acc, lane, warpm, warpn);
    __syncthreads();

    // fused local scan: 128 channels x 4 segments x 32 rows
    {
        const int ch  = tid & 127;
        const int seg = tid >> 7;
        const int chg = bx * 128 + ch;
        const float lr = g_pow_re[256 + chg], li = g_pow_im[256 + chg];

        float cr = 0.f, ci = 0.f;
#pragma unroll
        for (int i = 0; i < 32; i++) {
            int r = seg * 32 + i;
            float br = zs[r * ZST + ch];
            float bi = zs[r * ZST + 128 + ch];
            float t = fmaf(lr, cr, fmaf(-li, ci, br));
            ci      = fmaf(lr, ci, fmaf( li, cr, bi));
            cr = t;
        }
        float2* se = (float2*)(smem + SEG_OFF);
        se[seg * 128 + ch] = make_float2(cr, ci);
        __syncthreads();

        const float p32r = g_pow_re[32 * 256 + chg], p32i = g_pow_im[32 * 256 + chg];
        float gr = 0.f, gi = 0.f;
        for (int j = 0; j < seg; j++) {
            float2 e = se[j * 128 + ch];
            float t = fmaf(p32r, gr, fmaf(-p32i, gi, e.x));
            gi      = fmaf(p32r, gi, fmaf( p32i, gr, e.y));
            gr = t;
        }

        float wr = gr, wi = gi;
#pragma unroll
        for (int i = 0; i < 32; i++) {
            int r = seg * 32 + i;
            float br = zs[r * ZST + ch];
            float bi = zs[r * ZST + 128 + ch];
            float t = fmaf(lr, wr, fmaf(-li, wi, br));
            wi      = fmaf(lr, wi, fmaf( li, wr, bi));
            wr = t;
            size_t off = (size_t)(rowBase + r) * 512 + bx * 256;
            g_S[off + ch]       = wr;
            g_S[off + 128 + ch] = wi;
            if (seg == 3 && i == 31) g_ccar[by * 256 + chg] = make_float2(wr, wi);
        }
    }
}

// ---------------- K2: parallel carry scan ------------------------------------
__global__ __launch_bounds__(512) void k_carry()
{
    __shared__ float2 s[NCH];
    const int ch = blockIdx.x;
    const int t = threadIdx.x;
    s[t]       = g_ccar[t * 256 + ch];
    s[t + 512] = g_ccar[(t + 512) * 256 + ch];
    __syncthreads();
#pragma unroll
    for (int d = 0; d < 10; d++) {
        int st = 1 << d;
        float pr = g_cpow_re[d * 256 + ch];
        float pi = g_cpow_im[d * 256 + ch];
        int c0 = t, c1 = t + 512;
        float2 v0 = s[c0], v1 = s[c1];
        if (c0 >= st) {
            float2 w = s[c0 - st];
            v0.x = fmaf(pr, w.x, fmaf(-pi, w.y, v0.x));
            v0.y = fmaf(pr, w.y, fmaf( pi, w.x, v0.y));
        }
        {
            float2 w = s[c1 - st];
            v1.x = fmaf(pr, w.x, fmaf(-pi, w.y, v1.x));
            v1.y = fmaf(pr, w.y, fmaf( pi, w.x, v1.y));
        }
        __syncthreads();
        s[c0] = v0; s[c1] = v1;
        __syncthreads();
    }
    const int colre = ((ch >> 7) << 8) + (ch & 127);
    const int colim = colre + 128;
    float2 e0 = (t == 0) ? make_float2(0.f, 0.f) : s[t - 1];
    g_carP_re[t * 512 + colre] = e0.x;  g_carP_re[t * 512 + colim] = e0.x;
    g_carP_im[t * 512 + colre] = e0.y;  g_carP_im[t * 512 + colim] = e0.y;
    float2 e1 = s[t + 511];
    size_t o1 = (size_t)(t + 512) * 512;
    g_carP_re[o1 + colre] = e1.x;  g_carP_re[o1 + colim] = e1.x;
    g_carP_im[o1 + colre] = e1.y;  g_carP_im[o1 + colim] = e1.y;
}

// ---------------- K2b: correction + split pass -------------------------------
__global__ __launch_bounds__(512) void k_corr()
{
    const int chunk = blockIdx.x;
    const int tid = threadIdx.x;
    const int col = (tid & 255) * 2;
    const int rh  = tid >> 8;
    const int rowBase = chunk * CSZ;
    float2 cr = *(const float2*)&g_carP_re[(size_t)chunk * 512 + col];
    float2 ci = *(const float2*)&g_carP_im[(size_t)chunk * 512 + col];
#pragma unroll 4
    for (int i = 0; i < 64; i++) {
        int r = rh * 64 + i;
        size_t off = (size_t)(rowBase + r) * 512 + col;
        float2 s  = *(const float2*)&g_S[off];
        float2 qr = *(const float2*)&g_qr[(r + 1) * 512 + col];
        float2 qi = *(const float2*)&g_qi[(r + 1) * 512 + col];
        float v0 = s.x + qr.x * cr.x + qi.x * ci.x;
        float v1 = s.y + qr.y * cr.y + qi.y * ci.y;
        *(uint32_t*)&g_Shi[off] = pack_hi2(v0, v1);
        *(uint32_t*)&g_Slo[off] = pack_lo2(v0, v1);
    }
}

// ---------------- K3: output GEMM --------------------------------------------
__global__ __launch_bounds__(512, 1) void k_gemm2(const float* __restrict__ x,
                                                  const float* __restrict__ Dv,
                                                  float* __restrict__ out)
{
    extern __shared__ __align__(1024) char smem[];
    const int tid  = threadIdx.x;
    const int lane = tid & 31;
    const int warp = tid >> 5;
    const int warpm = warp & 1;
    const int warpn = warp >> 1;
    const int by = blockIdx.x;
    const int rowBase = by * CSZ;
    const uint32_t sm0 = smem_u32(smem);

    float acc[4][4][4];
#pragma unroll
    for (int mi = 0; mi < 4; mi++)
#pragma unroll
        for (int ni = 0; ni < 4; ni++)
#pragma unroll
            for (int j = 0; j < 4; j++) acc[mi][ni][j] = 0.f;

    const int rA = tid >> 3;
    const int gA = tid & 7;
    const uint32_t offA = ((gA ^ (rA & 7)) << 4);

    auto issue = [&](int c) {
        uint32_t sb = sm0 + (c & 1) * STAGE_BYTES;
        int k0 = c * 64;
        const __nv_bfloat16* ash = g_Shi + (size_t)(rowBase + rA) * 512 + k0 + gA * 8;
        const __nv_bfloat16* asl = g_Slo + (size_t)(rowBase + rA) * 512 + k0 + gA * 8;
        uint32_t dA = sb + rA * 128 + offA;
        CP_ASYNC(dA, ash);
        CP_ASYNC(dA + 16384, asl);
        CP_ASYNC(dA + 64 * 128, ash + (size_t)64 * 512);
        CP_ASYNC(dA + 16384 + 64 * 128, asl + (size_t)64 * 512);
#pragma unroll
        for (int rep = 0; rep < 4; rep++) {
            int id = tid + 512 * rep;
            int r = id >> 3, g = id & 7;
            uint32_t off = r * 128 + ((g ^ (r & 7)) << 4);
            const __nv_bfloat16* b0 = g_C2hi + (size_t)r * 512 + k0 + g * 8;
            const __nv_bfloat16* b1 = g_C2lo + (size_t)r * 512 + k0 + g * 8;
            CP_ASYNC(sb + 32768 + off, b0);
            CP_ASYNC(sb + 65536 + off, b1);
        }
        CP_COMMIT();
    };

    issue(0);
    const int NCC = 8;
    for (int c = 0; c < NCC; c++) {
        CP_WAIT0();
        __syncthreads();
        if (c + 1 < NCC) issue(c + 1);
        mma_stage(smem + (c & 1) * STAGE_BYTES, acc, lane, warpm, warpn);
        if (c + 1 < NCC) __syncthreads();
    }
    __syncthreads();

    float* zs = (float*)smem;
    acc_to_zs(zs, acc, lane, warpm, warpn);
    __syncthreads();

    // epilogue: y = zs + D*x   (full 256 cols)
    {
        int col = (tid & 63) * 4;
        float4 dv = *(const float4*)&Dv[col];
#pragma unroll
        for (int i = 0; i < 16; i++) {
            int r = (tid >> 6) + 8 * i;
            size_t l = (size_t)(rowBase + r);
            float4 xv = *(const float4*)&x[l * 256 + col];
            float4 o;
            o.x = zs[r * ZST + col + 0] + dv.x * xv.x;
            o.y = zs[r * ZST + col + 1] + dv.y * xv.y;
            o.z = zs[r * ZST + col + 2] + dv.z * xv.z;
            o.w = zs[r * ZST + col + 3] + dv.w * xv.w;
            *(float4*)(out + l * 256 + col) = o;
        }
    }
}

// ---------------- launch ----------------------------------------------------
extern "C" void kernel_launch(void* const* d_in, const int* in_sizes, int n_in,
                              void* d_out, int out_size)
{
    const float* x         = (const float*)d_in[0];
    const float* nu_log    = (const float*)d_in[1];
    const float* theta_log = (const float*)d_in[2];
    const float* B_re      = (const float*)d_in[3];
    const float* B_im      = (const float*)d_in[4];
    const float* C_re      = (const float*)d_in[5];
    const float* C_im      = (const float*)d_in[6];
    const float* Dv        = (const float*)d_in[7];
    const float* gamma_log = (const float*)d_in[8];
    float* out = (float*)d_out;

    cudaFuncSetAttribute(k_gemm1, cudaFuncAttributeMaxDynamicSharedMemorySize, SMEM_TOTAL);
    cudaFuncSetAttribute(k_gemm2, cudaFuncAttributeMaxDynamicSharedMemorySize, SMEM_TOTAL);

    k_setup<<<1, 256>>>(nu_log, theta_log, gamma_log);
    k_pack<<<768, 256>>>(B_re, B_im, C_re, C_im);
    k_prex<<<L_DIM * 256 / 1024, 256>>>(x);
    k_gemm1<<<dim3(2, 1024), 512, SMEM_TOTAL>>>();
    k_carry<<<256, 512>>>();
    k_corr<<<1024, 512>>>();
    k_gemm2<<<1024, 512, SMEM_TOTAL>>>(x, Dv, out);
}